// round 5
// baseline (speedup 1.0000x reference)
#include <cuda_runtime.h>
#include <math.h>

// ---------------------------------------------------------------------------
// Problem constants
// ---------------------------------------------------------------------------
#define BATCH 2
#define SEQ   2048
#define CH    768
#define HEADS 24
#define HD    32
#define L_PER_B (SEQ * CH)
#define TOT (BATCH * SEQ * CH)

__device__ float g_xn[TOT];
__device__ float g_q[TOT];
__device__ float g_vp[TOT];
__device__ float g_vr[TOT];
__device__ float g_res[TOT];
__device__ float g_h[TOT];
__device__ float g_h1[TOT];
__device__ float g_khi[TOT];
__device__ float g_klo[TOT];
__device__ float g_vhi[TOT];
__device__ float g_vlo[TOT];

// ---------------------------------------------------------------------------
// helpers
// ---------------------------------------------------------------------------
__device__ __forceinline__ float gelu_exact(float v)
{
    return 0.5f * v * (1.0f + erff(v * 0.7071067811865476f));
}

__device__ __forceinline__ unsigned cvt_tf32(float x)
{
    unsigned r;
    asm("cvt.rna.tf32.f32 %0, %1;" : "=r"(r) : "f"(x));
    return r;
}

__device__ __forceinline__ void tf32_split(float x, float& hi, float& lo)
{
    hi = __uint_as_float(cvt_tf32(x));
    lo = __uint_as_float(cvt_tf32(x - hi));
}

__device__ __forceinline__ void mma_tf32(float* c, const unsigned* a, const unsigned* b)
{
    asm volatile(
        "mma.sync.aligned.m16n8k8.row.col.f32.tf32.tf32.f32 "
        "{%0,%1,%2,%3}, {%4,%5,%6,%7}, {%8,%9}, {%0,%1,%2,%3};"
        : "+f"(c[0]), "+f"(c[1]), "+f"(c[2]), "+f"(c[3])
        : "r"(a[0]), "r"(a[1]), "r"(a[2]), "r"(a[3]), "r"(b[0]), "r"(b[1]));
}

__device__ __forceinline__ void cp_async16(void* smem, const void* gmem)
{
    asm volatile("cp.async.cg.shared.global [%0], [%1], 16;"
        :: "r"((unsigned)__cvta_generic_to_shared(smem)), "l"(gmem));
}
#define CP_COMMIT() asm volatile("cp.async.commit_group;")
#define CP_WAIT0()  asm volatile("cp.async.wait_group 0;")
#define CP_WAIT1()  asm volatile("cp.async.wait_group 1;")

// ---------------------------------------------------------------------------
// RMSNorm
// ---------------------------------------------------------------------------
__global__ __launch_bounds__(256)
void rmsnorm_kernel(const float* __restrict__ x, const float* __restrict__ g,
                    float* __restrict__ y)
{
    const int row = blockIdx.x;
    const int t = threadIdx.x;
    const float* xr = x + (long)row * CH;
    float v0 = xr[t], v1 = xr[t + 256], v2 = xr[t + 512];
    float ss = v0 * v0 + v1 * v1 + v2 * v2;

    __shared__ float red[8];
    #pragma unroll
    for (int o = 16; o > 0; o >>= 1) ss += __shfl_xor_sync(0xffffffffu, ss, o);
    if ((t & 31) == 0) red[t >> 5] = ss;
    __syncthreads();
    if (t < 8) {
        float s = red[t];
        #pragma unroll
        for (int o = 4; o > 0; o >>= 1) s += __shfl_xor_sync(0xffu, s, o);
        if (t == 0) red[0] = s;
    }
    __syncthreads();
    const float inv = rsqrtf(red[0] * (1.0f / 768.0f) + 1.1920928955078125e-07f);
    float* yr = y + (long)row * CH;
    yr[t]       = v0 * inv * g[t];
    yr[t + 256] = v1 * inv * g[t + 256];
    yr[t + 512] = v2 * inv * g[t + 512];
}

// ---------------------------------------------------------------------------
// Gather V' from the (H,N,HD) flat view
// ---------------------------------------------------------------------------
__global__ void gather_v_kernel(const float* __restrict__ xn, float* __restrict__ vp)
{
    long i = (long)blockIdx.x * blockDim.x + threadIdx.x;
    if (i >= (long)TOT) return;
    int b = (int)(i / L_PER_B);
    int rem = (int)(i - (long)b * L_PER_B);
    int m = rem / CH;
    int col = rem - m * CH;
    int h = col >> 5;
    int d = col & 31;
    vp[i] = xn[(long)b * L_PER_B + (long)h * (SEQ * HD) + m * HD + d];
}

// ---------------------------------------------------------------------------
// Split K (=xn) and V (=vr) into tf32 hi/lo pairs (once, reused by 16 q-blocks)
// ---------------------------------------------------------------------------
__global__ __launch_bounds__(256)
void split_kv_kernel(const float* __restrict__ xn, const float* __restrict__ vr,
                     float* __restrict__ khi, float* __restrict__ klo,
                     float* __restrict__ vhi, float* __restrict__ vlo)
{
    long i4 = (long)blockIdx.x * blockDim.x + threadIdx.x;
    if (i4 >= TOT / 4) return;
    float4 k = ((const float4*)xn)[i4];
    float4 v = ((const float4*)vr)[i4];
    float4 kh, kl, vh, vl;
    tf32_split(k.x, kh.x, kl.x); tf32_split(k.y, kh.y, kl.y);
    tf32_split(k.z, kh.z, kl.z); tf32_split(k.w, kh.w, kl.w);
    tf32_split(v.x, vh.x, vl.x); tf32_split(v.y, vh.y, vl.y);
    tf32_split(v.z, vh.z, vl.z); tf32_split(v.w, vh.w, vl.w);
    ((float4*)khi)[i4] = kh; ((float4*)klo)[i4] = kl;
    ((float4*)vhi)[i4] = vh; ((float4*)vlo)[i4] = vl;
}

// ---------------------------------------------------------------------------
// Pipelined TF32 tensor-core GEMM, cp.async 2-stage double buffer.
// 128x128x32 tile, 256 threads (8 warps 2x4), warp tile 64x32, m16n8k8.
//   NNMODE=true : C = A(MxK) @ B(KxN)
//   NNMODE=false: C = A(MxK) @ B(NxK)^T
//   COMP=true   : error-compensated 3xTF32 (fp32-grade, for logit-feeding GEMM)
// EPI: 0 none, 1 exact GELU, 2 add residual R
// Smem: raw fp32 staged; cvt to tf32 at fragment load.
// Dynamic smem: 2*4608 (A) + 2*4608 (B) floats = 73728 bytes.
// ---------------------------------------------------------------------------
#define GP_ABUF 4608
#define GP_SMEM_BYTES (4 * 4608 * 4)

template<bool NNMODE, bool COMP, int EPI>
__global__ __launch_bounds__(256)
void gemm_pl(const float* __restrict__ A, const float* __restrict__ B,
             float* __restrict__ C, const float* __restrict__ R,
             int M, int N, int K,
             long sA, long sB, long sC)
{
    extern __shared__ float smp[];
    float* Asm = smp;                 // [2][4608] rows of 36 (128x32)
    float* Bsm = smp + 2 * GP_ABUF;   // [2][4608] NN: [32][136] ; NT: [128][36]

    A += (long)blockIdx.z * sA;
    B += (long)blockIdx.z * sB;
    C += (long)blockIdx.z * sC;
    if (EPI == 2) R += (long)blockIdx.z * sC;

    const int t = threadIdx.x;
    const int w = t >> 5, lane = t & 31;
    const int g = lane >> 2, tg = lane & 3;
    const int wm = w >> 2, wn = w & 3;
    const int m0 = blockIdx.y * 128, n0 = blockIdx.x * 128;
    const int nk = K >> 5;

    // ---- stage tile k0 into buffer s (raw fp32, cp.async) ----
    auto stage = [&](int s, int k0) {
        float* as = Asm + s * GP_ABUF;
        float* bs = Bsm + s * GP_ABUF;
        #pragma unroll
        for (int i = 0; i < 4; i++) {
            const int f = t + i * 256;        // 1024 16B chunks
            const int row = f >> 3, d4 = (f & 7) * 4;
            cp_async16(&as[row * 36 + d4], A + (long)(m0 + row) * K + k0 + d4);
        }
        if (NNMODE) {
            #pragma unroll
            for (int i = 0; i < 4; i++) {
                const int f = t + i * 256;
                const int kk = f >> 5, n4 = (f & 31) * 4;
                cp_async16(&bs[kk * 136 + n4], B + (long)(k0 + kk) * N + n0 + n4);
            }
        } else {
            #pragma unroll
            for (int i = 0; i < 4; i++) {
                const int f = t + i * 256;
                const int row = f >> 3, d4 = (f & 7) * 4;
                cp_async16(&bs[row * 36 + d4], B + (long)(n0 + row) * K + k0 + d4);
            }
        }
    };

    float acc[4][4][4] = {};

    stage(0, 0);
    CP_COMMIT();

    for (int kt = 0; kt < nk; kt++) {
        if (kt + 1 < nk) {
            stage((kt + 1) & 1, (kt + 1) * 32);
            CP_COMMIT();
            CP_WAIT1();
        } else {
            CP_WAIT0();
        }
        __syncthreads();

        const float* as = Asm + (kt & 1) * GP_ABUF;
        const float* bs = Bsm + (kt & 1) * GP_ABUF;

        #pragma unroll
        for (int kc = 0; kc < 4; kc++) {
            const int kb = kc * 8;
            if (!COMP) {
                unsigned a[4][4], b[4][2];
                #pragma unroll
                for (int mt = 0; mt < 4; mt++) {
                    const int mr = wm * 64 + mt * 16 + g;
                    a[mt][0] = cvt_tf32(as[mr * 36 + kb + tg]);
                    a[mt][1] = cvt_tf32(as[(mr + 8) * 36 + kb + tg]);
                    a[mt][2] = cvt_tf32(as[mr * 36 + kb + tg + 4]);
                    a[mt][3] = cvt_tf32(as[(mr + 8) * 36 + kb + tg + 4]);
                }
                #pragma unroll
                for (int nt = 0; nt < 4; nt++) {
                    const int nc = wn * 32 + nt * 8 + g;
                    if (NNMODE) {
                        b[nt][0] = cvt_tf32(bs[(kb + tg) * 136 + nc]);
                        b[nt][1] = cvt_tf32(bs[(kb + tg + 4) * 136 + nc]);
                    } else {
                        b[nt][0] = cvt_tf32(bs[nc * 36 + kb + tg]);
                        b[nt][1] = cvt_tf32(bs[nc * 36 + kb + tg + 4]);
                    }
                }
                #pragma unroll
                for (int mt = 0; mt < 4; mt++)
                    #pragma unroll
                    for (int nt = 0; nt < 4; nt++)
                        mma_tf32(acc[mt][nt], a[mt], b[nt]);
            } else {
                unsigned ah[4][4], al[4][4], bh[4][2], bl[4][2];
                #pragma unroll
                for (int mt = 0; mt < 4; mt++) {
                    const int mr = wm * 64 + mt * 16 + g;
                    float x0 = as[mr * 36 + kb + tg];
                    float x1 = as[(mr + 8) * 36 + kb + tg];
                    float x2 = as[mr * 36 + kb + tg + 4];
                    float x3 = as[(mr + 8) * 36 + kb + tg + 4];
                    float h0, l0, h1, l1, h2, l2, h3, l3;
                    tf32_split(x0, h0, l0); tf32_split(x1, h1, l1);
                    tf32_split(x2, h2, l2); tf32_split(x3, h3, l3);
                    ah[mt][0] = __float_as_uint(h0); al[mt][0] = __float_as_uint(l0);
                    ah[mt][1] = __float_as_uint(h1); al[mt][1] = __float_as_uint(l1);
                    ah[mt][2] = __float_as_uint(h2); al[mt][2] = __float_as_uint(l2);
                    ah[mt][3] = __float_as_uint(h3); al[mt][3] = __float_as_uint(l3);
                }
                #pragma unroll
                for (int nt = 0; nt < 4; nt++) {
                    const int nc = wn * 32 + nt * 8 + g;
                    float x0, x1;
                    if (NNMODE) {
                        x0 = bs[(kb + tg) * 136 + nc];
                        x1 = bs[(kb + tg + 4) * 136 + nc];
                    } else {
                        x0 = bs[nc * 36 + kb + tg];
                        x1 = bs[nc * 36 + kb + tg + 4];
                    }
                    float h0, l0, h1, l1;
                    tf32_split(x0, h0, l0); tf32_split(x1, h1, l1);
                    bh[nt][0] = __float_as_uint(h0); bl[nt][0] = __float_as_uint(l0);
                    bh[nt][1] = __float_as_uint(h1); bl[nt][1] = __float_as_uint(l1);
                }
                #pragma unroll
                for (int mt = 0; mt < 4; mt++)
                    #pragma unroll
                    for (int nt = 0; nt < 4; nt++) {
                        mma_tf32(acc[mt][nt], ah[mt], bh[nt]);
                        mma_tf32(acc[mt][nt], ah[mt], bl[nt]);
                        mma_tf32(acc[mt][nt], al[mt], bh[nt]);
                    }
            }
        }
        __syncthreads();
    }

    #pragma unroll
    for (int mt = 0; mt < 4; mt++) {
        #pragma unroll
        for (int nt = 0; nt < 4; nt++) {
            const int row0 = m0 + wm * 64 + mt * 16 + g;
            const int col  = n0 + wn * 32 + nt * 8 + 2 * tg;
            float v0 = acc[mt][nt][0], v1 = acc[mt][nt][1];
            float v2 = acc[mt][nt][2], v3 = acc[mt][nt][3];
            if (EPI == 1) {
                v0 = gelu_exact(v0); v1 = gelu_exact(v1);
                v2 = gelu_exact(v2); v3 = gelu_exact(v3);
            } else if (EPI == 2) {
                float2 r0 = *(const float2*)(R + (long)row0 * N + col);
                float2 r1 = *(const float2*)(R + (long)(row0 + 8) * N + col);
                v0 += r0.x; v1 += r0.y; v2 += r1.x; v3 += r1.y;
            }
            float2 o0 = {v0, v1}, o1 = {v2, v3};
            *(float2*)(C + (long)row0 * N + col) = o0;
            *(float2*)(C + (long)(row0 + 8) * N + col) = o1;
        }
    }
}

// ---------------------------------------------------------------------------
// Tensor-core flash attention, 3xTF32, pre-split K/V, cp.async double buffer.
// 256 threads (8 warps), Br=128 q rows (warp m16), Bc=64 keys per tile.
// Smem floats:
//   ksh_hi[2][64*36] ksh_lo[2][64*36] vsh_hi[2][64*40] vsh_lo[2][64*40]
//   psh_hi[128*68] psh_lo[128*68]
// ---------------------------------------------------------------------------
#define F_KHI 0
#define F_KLO (F_KHI + 2 * 2304)
#define F_VHI (F_KLO + 2 * 2304)
#define F_VLO (F_VHI + 2 * 2560)
#define F_PHI (F_VLO + 2 * 2560)
#define F_PLO (F_PHI + 8704)
#define FLASH_SMEM_FLOATS (F_PLO + 8704)

__global__ __launch_bounds__(256)
void flash_tc(const float* __restrict__ Q,
              const float* __restrict__ Khi, const float* __restrict__ Klo,
              const float* __restrict__ Vhi, const float* __restrict__ Vlo,
              const float* __restrict__ X,
              const float* __restrict__ scale_param, float* __restrict__ O)
{
    extern __shared__ float sm[];
    float* psh_hi = sm + F_PHI;
    float* psh_lo = sm + F_PLO;

    const int b = blockIdx.z, h = blockIdx.y;
    const int t = threadIdx.x, w = t >> 5, lane = t & 31;
    const int g = lane >> 2, tg = lane & 3;
    const long baseqk = (long)b * L_PER_B + (long)h * (SEQ * HD);
    const long basev = (long)b * L_PER_B + h * HD;
    const float coef = logf(768.0f) * scale_param[h] * 5.656854249492381f;

    const int row0 = blockIdx.x * 128 + w * 16 + g;
    const int prow0 = w * 16 + g;

    // ---- stage tile kt into buffer s ----
    auto stage = [&](int s, int kt) {
        float* kh = sm + F_KHI + s * 2304;
        float* kl = sm + F_KLO + s * 2304;
        float* vh = sm + F_VHI + s * 2560;
        float* vl = sm + F_VLO + s * 2560;
        #pragma unroll
        for (int i = 0; i < 2; i++) {
            const int f = t + i * 256;        // 512 chunks per tensor
            const int row = f >> 3, d4 = (f & 7) * 4;
            const long ksrc = baseqk + (long)(kt * 64 + row) * HD + d4;
            const long vsrc = basev + (long)(kt * 64 + row) * CH + d4;
            cp_async16(&kh[row * 36 + d4], Khi + ksrc);
            cp_async16(&kl[row * 36 + d4], Klo + ksrc);
            cp_async16(&vh[row * 40 + d4], Vhi + vsrc);
            cp_async16(&vl[row * 40 + d4], Vlo + vsrc);
        }
    };

    // ---- Q fragments (loop-invariant), coef folded, hi/lo split ----
    unsigned qhi[4][4], qlo[4][4];
    #pragma unroll
    for (int kc = 0; kc < 4; kc++) {
        #pragma unroll
        for (int rr = 0; rr < 2; rr++) {
            const long base = baseqk + (long)(row0 + rr * 8) * HD + kc * 8 + tg;
            float x0 = Q[base] * coef;
            float x1 = Q[base + 4] * coef;
            float h0, l0, h1, l1;
            tf32_split(x0, h0, l0);
            tf32_split(x1, h1, l1);
            qhi[kc][rr]     = __float_as_uint(h0);
            qhi[kc][rr + 2] = __float_as_uint(h1);
            qlo[kc][rr]     = __float_as_uint(l0);
            qlo[kc][rr + 2] = __float_as_uint(l1);
        }
    }

    float acco[4][4] = {};
    float Mx[2] = {-1e30f, -1e30f};
    float Srun[2] = {0.0f, 0.0f};

    stage(0, 0);
    CP_COMMIT();

    for (int kt = 0; kt < SEQ / 64; kt++) {
        if (kt + 1 < SEQ / 64) {
            stage((kt + 1) & 1, kt + 1);
            CP_COMMIT();
            CP_WAIT1();
        } else {
            CP_WAIT0();
        }
        __syncthreads();

        const int s = kt & 1;
        const float* ksh_hi = sm + F_KHI + s * 2304;
        const float* ksh_lo = sm + F_KLO + s * 2304;
        const float* vsh_hi = sm + F_VHI + s * 2560;
        const float* vsh_lo = sm + F_VLO + s * 2560;

        // ---- S = Q K^T (3xTF32) ----
        float accs[8][4] = {};
        #pragma unroll
        for (int kc = 0; kc < 4; kc++) {
            const int kb = kc * 8;
            #pragma unroll
            for (int nt = 0; nt < 8; nt++) {
                const int key = nt * 8 + g;
                unsigned bhi[2], blo[2];
                bhi[0] = __float_as_uint(ksh_hi[key * 36 + kb + tg]);
                bhi[1] = __float_as_uint(ksh_hi[key * 36 + kb + tg + 4]);
                blo[0] = __float_as_uint(ksh_lo[key * 36 + kb + tg]);
                blo[1] = __float_as_uint(ksh_lo[key * 36 + kb + tg + 4]);
                mma_tf32(accs[nt], qhi[kc], bhi);
                mma_tf32(accs[nt], qhi[kc], blo);
                mma_tf32(accs[nt], qlo[kc], bhi);
            }
        }

        // ---- online softmax ----
        #pragma unroll
        for (int rr = 0; rr < 2; rr++) {
            const int i0 = rr * 2, i1 = rr * 2 + 1;
            float m = accs[0][i0];
            #pragma unroll
            for (int nt = 0; nt < 8; nt++) {
                m = fmaxf(m, accs[nt][i0]);
                m = fmaxf(m, accs[nt][i1]);
            }
            m = fmaxf(m, __shfl_xor_sync(0xffffffffu, m, 1));
            m = fmaxf(m, __shfl_xor_sync(0xffffffffu, m, 2));
            const float Mn = fmaxf(Mx[rr], m);
            const float corr = __expf(Mx[rr] - Mn);
            Srun[rr] *= corr;
            #pragma unroll
            for (int nt = 0; nt < 4; nt++) {
                acco[nt][i0] *= corr;
                acco[nt][i1] *= corr;
            }
            Mx[rr] = Mn;
            float lsum = 0.0f;
            const int pr = (prow0 + rr * 8) * 68;
            #pragma unroll
            for (int nt = 0; nt < 8; nt++) {
                const float p0 = __expf(accs[nt][i0] - Mn);
                const float p1 = __expf(accs[nt][i1] - Mn);
                lsum += p0 + p1;
                float h0, l0, h1, l1;
                tf32_split(p0, h0, l0);
                tf32_split(p1, h1, l1);
                const int col = nt * 8 + 2 * tg;
                float2 ph = {h0, h1}, pl = {l0, l1};
                *(float2*)&psh_hi[pr + col] = ph;
                *(float2*)&psh_lo[pr + col] = pl;
            }
            lsum += __shfl_xor_sync(0xffffffffu, lsum, 1);
            lsum += __shfl_xor_sync(0xffffffffu, lsum, 2);
            Srun[rr] += lsum;
        }
        __syncwarp();

        // ---- O += P V (3xTF32) ----
        #pragma unroll
        for (int kc = 0; kc < 8; kc++) {
            const int kb = kc * 8;
            unsigned phi[4], plo[4];
            phi[0] = __float_as_uint(psh_hi[prow0 * 68 + kb + tg]);
            phi[1] = __float_as_uint(psh_hi[(prow0 + 8) * 68 + kb + tg]);
            phi[2] = __float_as_uint(psh_hi[prow0 * 68 + kb + tg + 4]);
            phi[3] = __float_as_uint(psh_hi[(prow0 + 8) * 68 + kb + tg + 4]);
            plo[0] = __float_as_uint(psh_lo[prow0 * 68 + kb + tg]);
            plo[1] = __float_as_uint(psh_lo[(prow0 + 8) * 68 + kb + tg]);
            plo[2] = __float_as_uint(psh_lo[prow0 * 68 + kb + tg + 4]);
            plo[3] = __float_as_uint(psh_lo[(prow0 + 8) * 68 + kb + tg + 4]);
            #pragma unroll
            for (int nt = 0; nt < 4; nt++) {
                unsigned bhi[2], blo[2];
                bhi[0] = __float_as_uint(vsh_hi[(kb + tg) * 40 + nt * 8 + g]);
                bhi[1] = __float_as_uint(vsh_hi[(kb + tg + 4) * 40 + nt * 8 + g]);
                blo[0] = __float_as_uint(vsh_lo[(kb + tg) * 40 + nt * 8 + g]);
                blo[1] = __float_as_uint(vsh_lo[(kb + tg + 4) * 40 + nt * 8 + g]);
                mma_tf32(acco[nt], phi, bhi);
                mma_tf32(acco[nt], phi, blo);
                mma_tf32(acco[nt], plo, bhi);
            }
        }
        __syncthreads();
    }

    // ---- epilogue: /S, +x, store ----
    const float inv0 = 1.0f / Srun[0];
    const float inv1 = 1.0f / Srun[1];
    #pragma unroll
    for (int nt = 0; nt < 4; nt++) {
        const int col = nt * 8 + 2 * tg;
        const long a0 = baseqk + (long)row0 * HD + col;
        const long a1 = baseqk + (long)(row0 + 8) * HD + col;
        float2 x0 = *(const float2*)(X + a0);
        float2 x1 = *(const float2*)(X + a1);
        float2 o0 = {acco[nt][0] * inv0 + x0.x, acco[nt][1] * inv0 + x0.y};
        float2 o1 = {acco[nt][2] * inv1 + x1.x, acco[nt][3] * inv1 + x1.y};
        *(float2*)(O + a0) = o0;
        *(float2*)(O + a1) = o1;
    }
}

// ---------------------------------------------------------------------------
// Launch
// ---------------------------------------------------------------------------
extern "C" void kernel_launch(void* const* d_in, const int* in_sizes, int n_in,
                              void* d_out, int out_size)
{
    const float* x     = (const float*)d_in[0];
    const float* scale = (const float*)d_in[1];
    const float* Wq    = (const float*)d_in[2];
    const float* WA    = (const float*)d_in[3];
    const float* W1    = (const float*)d_in[4];
    const float* W2    = (const float*)d_in[5];
    const float* g1    = (const float*)d_in[6];
    const float* g2    = (const float*)d_in[7];
    float* out = (float*)d_out;

    float *xn, *q, *vp, *vr, *res, *hh, *h1, *khi, *klo, *vhi, *vlo;
    cudaGetSymbolAddress((void**)&xn,  g_xn);
    cudaGetSymbolAddress((void**)&q,   g_q);
    cudaGetSymbolAddress((void**)&vp,  g_vp);
    cudaGetSymbolAddress((void**)&vr,  g_vr);
    cudaGetSymbolAddress((void**)&res, g_res);
    cudaGetSymbolAddress((void**)&hh,  g_h);
    cudaGetSymbolAddress((void**)&h1,  g_h1);
    cudaGetSymbolAddress((void**)&khi, g_khi);
    cudaGetSymbolAddress((void**)&klo, g_klo);
    cudaGetSymbolAddress((void**)&vhi, g_vhi);
    cudaGetSymbolAddress((void**)&vlo, g_vlo);

    const int ROWS = BATCH * SEQ;  // 4096
    const int flashSmem = FLASH_SMEM_FLOATS * 4;

    cudaFuncSetAttribute(flash_tc, cudaFuncAttributeMaxDynamicSharedMemorySize,
                         flashSmem);
    cudaFuncSetAttribute(gemm_pl<true, false, 0>,
                         cudaFuncAttributeMaxDynamicSharedMemorySize, GP_SMEM_BYTES);
    cudaFuncSetAttribute(gemm_pl<false, true, 0>,
                         cudaFuncAttributeMaxDynamicSharedMemorySize, GP_SMEM_BYTES);
    cudaFuncSetAttribute(gemm_pl<false, false, 1>,
                         cudaFuncAttributeMaxDynamicSharedMemorySize, GP_SMEM_BYTES);
    cudaFuncSetAttribute(gemm_pl<false, false, 2>,
                         cudaFuncAttributeMaxDynamicSharedMemorySize, GP_SMEM_BYTES);

    // 1. xn = rmsnorm(x, g1)
    rmsnorm_kernel<<<ROWS, 256>>>(x, g1, xn);

    // 2. q = xn @ Wq^T   (compensated 3xTF32 — feeds logits, fp32-grade)
    gemm_pl<false, true, 0><<<dim3(CH / 128, ROWS / 128, 1), 256, GP_SMEM_BYTES>>>(
        xn, Wq, q, nullptr, ROWS, CH, CH, 0, 0, 0);

    // 3. gather V'
    gather_v_kernel<<<(TOT + 255) / 256, 256>>>(xn, vp);

    // 4. vr[b] = WA @ vp[b]   (single tf32, pipelined)
    gemm_pl<true, false, 0><<<dim3(CH / 128, SEQ / 128, BATCH), 256, GP_SMEM_BYTES>>>(
        WA, vp, vr, nullptr, SEQ, CH, SEQ, 0, (long)SEQ * CH, (long)SEQ * CH);

    // 5. pre-split K (=xn) and V (=vr) into tf32 hi/lo
    split_kv_kernel<<<(TOT / 4 + 255) / 256, 256>>>(xn, vr, khi, klo, vhi, vlo);

    // 6. attention (+x residual)
    flash_tc<<<dim3(SEQ / 128, HEADS, BATCH), 256, flashSmem>>>(
        q, khi, klo, vhi, vlo, x, scale, res);

    // 7. hh = rmsnorm(res, g2)
    rmsnorm_kernel<<<ROWS, 256>>>(res, g2, hh);

    // 8. h1 = gelu(hh @ W1^T)
    gemm_pl<false, false, 1><<<dim3(CH / 128, ROWS / 128, 1), 256, GP_SMEM_BYTES>>>(
        hh, W1, h1, nullptr, ROWS, CH, CH, 0, 0, 0);

    // 9. out = h1 @ W2^T + res
    gemm_pl<false, false, 2><<<dim3(CH / 128, ROWS / 128, 1), 256, GP_SMEM_BYTES>>>(
        h1, W2, out, res, ROWS, CH, CH, 0, 0, 0);
}

// round 7
// speedup vs baseline: 1.1721x; 1.1721x over previous
#include <cuda_runtime.h>
#include <math.h>

// ---------------------------------------------------------------------------
// Problem constants
// ---------------------------------------------------------------------------
#define BATCH 2
#define SEQ   2048
#define CH    768
#define HEADS 24
#define HD    32
#define L_PER_B (SEQ * CH)
#define TOT (BATCH * SEQ * CH)

__device__ float g_xn[TOT];
__device__ float g_q[TOT];
__device__ float g_vp[TOT];
__device__ float g_vr[TOT];
__device__ float g_res[TOT];
__device__ float g_h[TOT];
__device__ float g_h1[TOT];
__device__ float g_khi[TOT];
__device__ float g_klo[TOT];
__device__ float g_vhi[TOT];
__device__ float g_vlo[TOT];

// ---------------------------------------------------------------------------
// helpers
// ---------------------------------------------------------------------------
__device__ __forceinline__ float gelu_exact(float v)
{
    return 0.5f * v * (1.0f + erff(v * 0.7071067811865476f));
}

__device__ __forceinline__ unsigned cvt_tf32(float x)
{
    unsigned r;
    asm("cvt.rna.tf32.f32 %0, %1;" : "=r"(r) : "f"(x));
    return r;
}

__device__ __forceinline__ void tf32_split(float x, float& hi, float& lo)
{
    hi = __uint_as_float(cvt_tf32(x));
    lo = __uint_as_float(cvt_tf32(x - hi));
}

__device__ __forceinline__ void mma_tf32(float* c, const unsigned* a, const unsigned* b)
{
    asm volatile(
        "mma.sync.aligned.m16n8k8.row.col.f32.tf32.tf32.f32 "
        "{%0,%1,%2,%3}, {%4,%5,%6,%7}, {%8,%9}, {%0,%1,%2,%3};"
        : "+f"(c[0]), "+f"(c[1]), "+f"(c[2]), "+f"(c[3])
        : "r"(a[0]), "r"(a[1]), "r"(a[2]), "r"(a[3]), "r"(b[0]), "r"(b[1]));
}

__device__ __forceinline__ void cp_async16(void* smem, const void* gmem)
{
    asm volatile("cp.async.cg.shared.global [%0], [%1], 16;"
        :: "r"((unsigned)__cvta_generic_to_shared(smem)), "l"(gmem));
}
#define CP_COMMIT() asm volatile("cp.async.commit_group;")
#define CP_WAIT0()  asm volatile("cp.async.wait_group 0;")
#define CP_WAIT1()  asm volatile("cp.async.wait_group 1;")

// ---------------------------------------------------------------------------
// RMSNorm
// ---------------------------------------------------------------------------
__global__ __launch_bounds__(256)
void rmsnorm_kernel(const float* __restrict__ x, const float* __restrict__ g,
                    float* __restrict__ y)
{
    const int row = blockIdx.x;
    const int t = threadIdx.x;
    const float* xr = x + (long)row * CH;
    float v0 = xr[t], v1 = xr[t + 256], v2 = xr[t + 512];
    float ss = v0 * v0 + v1 * v1 + v2 * v2;

    __shared__ float red[8];
    #pragma unroll
    for (int o = 16; o > 0; o >>= 1) ss += __shfl_xor_sync(0xffffffffu, ss, o);
    if ((t & 31) == 0) red[t >> 5] = ss;
    __syncthreads();
    if (t < 8) {
        float s = red[t];
        #pragma unroll
        for (int o = 4; o > 0; o >>= 1) s += __shfl_xor_sync(0xffu, s, o);
        if (t == 0) red[0] = s;
    }
    __syncthreads();
    const float inv = rsqrtf(red[0] * (1.0f / 768.0f) + 1.1920928955078125e-07f);
    float* yr = y + (long)row * CH;
    yr[t]       = v0 * inv * g[t];
    yr[t + 256] = v1 * inv * g[t + 256];
    yr[t + 512] = v2 * inv * g[t + 512];
}

// ---------------------------------------------------------------------------
// Gather V' from the (H,N,HD) flat view
// ---------------------------------------------------------------------------
__global__ void gather_v_kernel(const float* __restrict__ xn, float* __restrict__ vp)
{
    long i = (long)blockIdx.x * blockDim.x + threadIdx.x;
    if (i >= (long)TOT) return;
    int b = (int)(i / L_PER_B);
    int rem = (int)(i - (long)b * L_PER_B);
    int m = rem / CH;
    int col = rem - m * CH;
    int h = col >> 5;
    int d = col & 31;
    vp[i] = xn[(long)b * L_PER_B + (long)h * (SEQ * HD) + m * HD + d];
}

// ---------------------------------------------------------------------------
// tf32 hi/lo split of one buffer
// ---------------------------------------------------------------------------
__global__ __launch_bounds__(256)
void split_kernel(const float* __restrict__ src,
                  float* __restrict__ hi, float* __restrict__ lo)
{
    long i4 = (long)blockIdx.x * blockDim.x + threadIdx.x;
    if (i4 >= TOT / 4) return;
    float4 v = ((const float4*)src)[i4];
    float4 h, l;
    tf32_split(v.x, h.x, l.x); tf32_split(v.y, h.y, l.y);
    tf32_split(v.z, h.z, l.z); tf32_split(v.w, h.w, l.w);
    ((float4*)hi)[i4] = h; ((float4*)lo)[i4] = l;
}

// ---------------------------------------------------------------------------
// Pipelined single-pass TF32 GEMM (premix / MLP), cp.async double buffer.
//   NNMODE=true : C = A(MxK) @ B(KxN)
//   NNMODE=false: C = A(MxK) @ B(NxK)^T
// EPI: 0 none, 1 exact GELU, 2 add residual R
// ---------------------------------------------------------------------------
#define GP_ABUF 4608
#define GP_SMEM_BYTES (4 * 4608 * 4)

template<bool NNMODE, int EPI>
__global__ __launch_bounds__(256)
void gemm_pl(const float* __restrict__ A, const float* __restrict__ B,
             float* __restrict__ C, const float* __restrict__ R,
             int M, int N, int K,
             long sA, long sB, long sC)
{
    extern __shared__ float smp[];
    float* Asm = smp;
    float* Bsm = smp + 2 * GP_ABUF;

    A += (long)blockIdx.z * sA;
    B += (long)blockIdx.z * sB;
    C += (long)blockIdx.z * sC;
    if (EPI == 2) R += (long)blockIdx.z * sC;

    const int t = threadIdx.x;
    const int w = t >> 5, lane = t & 31;
    const int g = lane >> 2, tg = lane & 3;
    const int wm = w >> 2, wn = w & 3;
    const int m0 = blockIdx.y * 128, n0 = blockIdx.x * 128;
    const int nk = K >> 5;

    auto stage = [&](int s, int k0) {
        float* as = Asm + s * GP_ABUF;
        float* bs = Bsm + s * GP_ABUF;
        #pragma unroll
        for (int i = 0; i < 4; i++) {
            const int f = t + i * 256;
            const int row = f >> 3, d4 = (f & 7) * 4;
            cp_async16(&as[row * 36 + d4], A + (long)(m0 + row) * K + k0 + d4);
        }
        if (NNMODE) {
            #pragma unroll
            for (int i = 0; i < 4; i++) {
                const int f = t + i * 256;
                const int kk = f >> 5, n4 = (f & 31) * 4;
                cp_async16(&bs[kk * 136 + n4], B + (long)(k0 + kk) * N + n0 + n4);
            }
        } else {
            #pragma unroll
            for (int i = 0; i < 4; i++) {
                const int f = t + i * 256;
                const int row = f >> 3, d4 = (f & 7) * 4;
                cp_async16(&bs[row * 36 + d4], B + (long)(n0 + row) * K + k0 + d4);
            }
        }
    };

    float acc[4][4][4] = {};

    stage(0, 0);
    CP_COMMIT();

    for (int kt = 0; kt < nk; kt++) {
        if (kt + 1 < nk) {
            stage((kt + 1) & 1, (kt + 1) * 32);
            CP_COMMIT();
            CP_WAIT1();
        } else {
            CP_WAIT0();
        }
        __syncthreads();

        const float* as = Asm + (kt & 1) * GP_ABUF;
        const float* bs = Bsm + (kt & 1) * GP_ABUF;

        #pragma unroll
        for (int kc = 0; kc < 4; kc++) {
            const int kb = kc * 8;
            unsigned a[4][4], b[4][2];
            #pragma unroll
            for (int mt = 0; mt < 4; mt++) {
                const int mr = wm * 64 + mt * 16 + g;
                a[mt][0] = cvt_tf32(as[mr * 36 + kb + tg]);
                a[mt][1] = cvt_tf32(as[(mr + 8) * 36 + kb + tg]);
                a[mt][2] = cvt_tf32(as[mr * 36 + kb + tg + 4]);
                a[mt][3] = cvt_tf32(as[(mr + 8) * 36 + kb + tg + 4]);
            }
            #pragma unroll
            for (int nt = 0; nt < 4; nt++) {
                const int nc = wn * 32 + nt * 8 + g;
                if (NNMODE) {
                    b[nt][0] = cvt_tf32(bs[(kb + tg) * 136 + nc]);
                    b[nt][1] = cvt_tf32(bs[(kb + tg + 4) * 136 + nc]);
                } else {
                    b[nt][0] = cvt_tf32(bs[nc * 36 + kb + tg]);
                    b[nt][1] = cvt_tf32(bs[nc * 36 + kb + tg + 4]);
                }
            }
            #pragma unroll
            for (int mt = 0; mt < 4; mt++)
                #pragma unroll
                for (int nt = 0; nt < 4; nt++)
                    mma_tf32(acc[mt][nt], a[mt], b[nt]);
        }
        __syncthreads();
    }

    #pragma unroll
    for (int mt = 0; mt < 4; mt++) {
        #pragma unroll
        for (int nt = 0; nt < 4; nt++) {
            const int row0 = m0 + wm * 64 + mt * 16 + g;
            const int col  = n0 + wn * 32 + nt * 8 + 2 * tg;
            float v0 = acc[mt][nt][0], v1 = acc[mt][nt][1];
            float v2 = acc[mt][nt][2], v3 = acc[mt][nt][3];
            if (EPI == 1) {
                v0 = gelu_exact(v0); v1 = gelu_exact(v1);
                v2 = gelu_exact(v2); v3 = gelu_exact(v3);
            } else if (EPI == 2) {
                float2 r0 = *(const float2*)(R + (long)row0 * N + col);
                float2 r1 = *(const float2*)(R + (long)(row0 + 8) * N + col);
                v0 += r0.x; v1 += r0.y; v2 += r1.x; v3 += r1.y;
            }
            float2 o0 = {v0, v1}, o1 = {v2, v3};
            *(float2*)(C + (long)row0 * N + col) = o0;
            *(float2*)(C + (long)(row0 + 8) * N + col) = o1;
        }
    }
}

// ---------------------------------------------------------------------------
// Wq projection: compensated 3xTF32 NT GEMM with PRE-SPLIT A (khi/klo).
// C[m,n] = sum_k A[m,k]*B[n,k]; B (Wq) split in-loop.
// Smem: Ahi/Alo/B x 2 buffers x 4608 floats = 110592 bytes.
// ---------------------------------------------------------------------------
#define WQ_SMEM_BYTES (6 * 4608 * 4)

__global__ __launch_bounds__(256)
void gemm_wq(const float* __restrict__ Ahi, const float* __restrict__ Alo,
             const float* __restrict__ B, float* __restrict__ C,
             int M, int N, int K)
{
    extern __shared__ float smw[];
    float* AHs = smw;
    float* ALs = smw + 2 * GP_ABUF;
    float* Bs  = smw + 4 * GP_ABUF;

    const int t = threadIdx.x;
    const int w = t >> 5, lane = t & 31;
    const int g = lane >> 2, tg = lane & 3;
    const int wm = w >> 2, wn = w & 3;
    const int m0 = blockIdx.y * 128, n0 = blockIdx.x * 128;
    const int nk = K >> 5;

    auto stage = [&](int s, int k0) {
        float* ah = AHs + s * GP_ABUF;
        float* al = ALs + s * GP_ABUF;
        float* bs = Bs + s * GP_ABUF;
        #pragma unroll
        for (int i = 0; i < 4; i++) {
            const int f = t + i * 256;
            const int row = f >> 3, d4 = (f & 7) * 4;
            cp_async16(&ah[row * 36 + d4], Ahi + (long)(m0 + row) * K + k0 + d4);
            cp_async16(&al[row * 36 + d4], Alo + (long)(m0 + row) * K + k0 + d4);
            cp_async16(&bs[row * 36 + d4], B + (long)(n0 + row) * K + k0 + d4);
        }
    };

    float acc[4][4][4] = {};

    stage(0, 0);
    CP_COMMIT();

    for (int kt = 0; kt < nk; kt++) {
        if (kt + 1 < nk) {
            stage((kt + 1) & 1, (kt + 1) * 32);
            CP_COMMIT();
            CP_WAIT1();
        } else {
            CP_WAIT0();
        }
        __syncthreads();

        const float* ah = AHs + (kt & 1) * GP_ABUF;
        const float* al = ALs + (kt & 1) * GP_ABUF;
        const float* bs = Bs + (kt & 1) * GP_ABUF;

        #pragma unroll
        for (int kc = 0; kc < 4; kc++) {
            const int kb = kc * 8;
            unsigned aH[4][4], aL[4][4], bH[4][2], bL[4][2];
            #pragma unroll
            for (int mt = 0; mt < 4; mt++) {
                const int mr = wm * 64 + mt * 16 + g;
                aH[mt][0] = __float_as_uint(ah[mr * 36 + kb + tg]);
                aH[mt][1] = __float_as_uint(ah[(mr + 8) * 36 + kb + tg]);
                aH[mt][2] = __float_as_uint(ah[mr * 36 + kb + tg + 4]);
                aH[mt][3] = __float_as_uint(ah[(mr + 8) * 36 + kb + tg + 4]);
                aL[mt][0] = __float_as_uint(al[mr * 36 + kb + tg]);
                aL[mt][1] = __float_as_uint(al[(mr + 8) * 36 + kb + tg]);
                aL[mt][2] = __float_as_uint(al[mr * 36 + kb + tg + 4]);
                aL[mt][3] = __float_as_uint(al[(mr + 8) * 36 + kb + tg + 4]);
            }
            #pragma unroll
            for (int nt = 0; nt < 4; nt++) {
                const int nc = wn * 32 + nt * 8 + g;
                float x0 = bs[nc * 36 + kb + tg];
                float x1 = bs[nc * 36 + kb + tg + 4];
                float h0, l0, h1, l1;
                tf32_split(x0, h0, l0); tf32_split(x1, h1, l1);
                bH[nt][0] = __float_as_uint(h0); bL[nt][0] = __float_as_uint(l0);
                bH[nt][1] = __float_as_uint(h1); bL[nt][1] = __float_as_uint(l1);
            }
            #pragma unroll
            for (int mt = 0; mt < 4; mt++)
                #pragma unroll
                for (int nt = 0; nt < 4; nt++) {
                    mma_tf32(acc[mt][nt], aH[mt], bH[nt]);
                    mma_tf32(acc[mt][nt], aH[mt], bL[nt]);
                    mma_tf32(acc[mt][nt], aL[mt], bH[nt]);
                }
        }
        __syncthreads();
    }

    #pragma unroll
    for (int mt = 0; mt < 4; mt++) {
        #pragma unroll
        for (int nt = 0; nt < 4; nt++) {
            const int row0 = m0 + wm * 64 + mt * 16 + g;
            const int col  = n0 + wn * 32 + nt * 8 + 2 * tg;
            float2 o0 = {acc[mt][nt][0], acc[mt][nt][1]};
            float2 o1 = {acc[mt][nt][2], acc[mt][nt][3]};
            *(float2*)(C + (long)row0 * N + col) = o0;
            *(float2*)(C + (long)(row0 + 8) * N + col) = o1;
        }
    }
}

// ---------------------------------------------------------------------------
// Tensor-core flash attention.
// QK: 3xTF32 (fp32-grade logits). PV: 2-term (p_hi*v_hi + p_hi*v_lo).
// P relayout via quad shuffles (no smem round trip).
// 256 threads, Br=128 q rows, Bc=64 keys/tile, cp.async double buffer.
// Smem: K hi/lo [2][64*36], V hi/lo [2][64*40] = 77824 bytes -> 2 blocks/SM.
// ---------------------------------------------------------------------------
#define F_KHI 0
#define F_KLO (F_KHI + 2 * 2304)
#define F_VHI (F_KLO + 2 * 2304)
#define F_VLO (F_VHI + 2 * 2560)
#define FLASH_SMEM_FLOATS (F_VLO + 2 * 2560)

__global__ __launch_bounds__(256, 2)
void flash_tc(const float* __restrict__ Q,
              const float* __restrict__ Khi, const float* __restrict__ Klo,
              const float* __restrict__ Vhi, const float* __restrict__ Vlo,
              const float* __restrict__ X,
              const float* __restrict__ scale_param, float* __restrict__ O)
{
    extern __shared__ float sm[];

    const int b = blockIdx.z, h = blockIdx.y;
    const int t = threadIdx.x, w = t >> 5, lane = t & 31;
    const int g = lane >> 2, tg = lane & 3;
    const long baseqk = (long)b * L_PER_B + (long)h * (SEQ * HD);
    const long basev = (long)b * L_PER_B + h * HD;
    const float coef = logf(768.0f) * scale_param[h] * 5.656854249492381f;

    const int row0 = blockIdx.x * 128 + w * 16 + g;

    auto stage = [&](int s, int kt) {
        float* kh = sm + F_KHI + s * 2304;
        float* kl = sm + F_KLO + s * 2304;
        float* vh = sm + F_VHI + s * 2560;
        float* vl = sm + F_VLO + s * 2560;
        #pragma unroll
        for (int i = 0; i < 2; i++) {
            const int f = t + i * 256;
            const int row = f >> 3, d4 = (f & 7) * 4;
            const long ksrc = baseqk + (long)(kt * 64 + row) * HD + d4;
            const long vsrc = basev + (long)(kt * 64 + row) * CH + d4;
            cp_async16(&kh[row * 36 + d4], Khi + ksrc);
            cp_async16(&kl[row * 36 + d4], Klo + ksrc);
            cp_async16(&vh[row * 40 + d4], Vhi + vsrc);
            cp_async16(&vl[row * 40 + d4], Vlo + vsrc);
        }
    };

    // ---- Q fragments (loop-invariant), coef folded, hi/lo split ----
    unsigned qhi[4][4], qlo[4][4];
    #pragma unroll
    for (int kc = 0; kc < 4; kc++) {
        #pragma unroll
        for (int rr = 0; rr < 2; rr++) {
            const long base = baseqk + (long)(row0 + rr * 8) * HD + kc * 8 + tg;
            float x0 = Q[base] * coef;
            float x1 = Q[base + 4] * coef;
            float h0, l0, h1, l1;
            tf32_split(x0, h0, l0);
            tf32_split(x1, h1, l1);
            qhi[kc][rr]     = __float_as_uint(h0);
            qhi[kc][rr + 2] = __float_as_uint(h1);
            qlo[kc][rr]     = __float_as_uint(l0);
            qlo[kc][rr + 2] = __float_as_uint(l1);
        }
    }

    float acco[4][4] = {};
    float Mx[2] = {-1e30f, -1e30f};
    float Srun[2] = {0.0f, 0.0f};

    const unsigned full = 0xffffffffu;
    const int srcA = (lane & ~3) + (tg >> 1);
    const int srcB = srcA + 2;

    stage(0, 0);
    CP_COMMIT();

    for (int kt = 0; kt < SEQ / 64; kt++) {
        if (kt + 1 < SEQ / 64) {
            stage((kt + 1) & 1, kt + 1);
            CP_COMMIT();
            CP_WAIT1();
        } else {
            CP_WAIT0();
        }
        __syncthreads();

        const int s = kt & 1;
        const float* ksh_hi = sm + F_KHI + s * 2304;
        const float* ksh_lo = sm + F_KLO + s * 2304;
        const float* vsh_hi = sm + F_VHI + s * 2560;
        const float* vsh_lo = sm + F_VLO + s * 2560;

        // ---- S = Q K^T (3xTF32) ----
        float accs[8][4] = {};
        #pragma unroll
        for (int kc = 0; kc < 4; kc++) {
            const int kb = kc * 8;
            #pragma unroll
            for (int nt = 0; nt < 8; nt++) {
                const int key = nt * 8 + g;
                unsigned bhi[2], blo[2];
                bhi[0] = __float_as_uint(ksh_hi[key * 36 + kb + tg]);
                bhi[1] = __float_as_uint(ksh_hi[key * 36 + kb + tg + 4]);
                blo[0] = __float_as_uint(ksh_lo[key * 36 + kb + tg]);
                blo[1] = __float_as_uint(ksh_lo[key * 36 + kb + tg + 4]);
                mma_tf32(accs[nt], qhi[kc], bhi);
                mma_tf32(accs[nt], qhi[kc], blo);
                mma_tf32(accs[nt], qlo[kc], bhi);
            }
        }

        // ---- online softmax; p overwrites accs ----
        #pragma unroll
        for (int rr = 0; rr < 2; rr++) {
            const int i0 = rr * 2, i1 = rr * 2 + 1;
            float m = accs[0][i0];
            #pragma unroll
            for (int nt = 0; nt < 8; nt++) {
                m = fmaxf(m, accs[nt][i0]);
                m = fmaxf(m, accs[nt][i1]);
            }
            m = fmaxf(m, __shfl_xor_sync(full, m, 1));
            m = fmaxf(m, __shfl_xor_sync(full, m, 2));
            const float Mn = fmaxf(Mx[rr], m);
            const float corr = __expf(Mx[rr] - Mn);
            Srun[rr] *= corr;
            #pragma unroll
            for (int nt = 0; nt < 4; nt++) {
                acco[nt][i0] *= corr;
                acco[nt][i1] *= corr;
            }
            Mx[rr] = Mn;
            float lsum = 0.0f;
            #pragma unroll
            for (int nt = 0; nt < 8; nt++) {
                const float p0 = __expf(accs[nt][i0] - Mn);
                const float p1 = __expf(accs[nt][i1] - Mn);
                lsum += p0 + p1;
                accs[nt][i0] = p0;
                accs[nt][i1] = p1;
            }
            lsum += __shfl_xor_sync(full, lsum, 1);
            lsum += __shfl_xor_sync(full, lsum, 2);
            Srun[rr] += lsum;
        }

        // ---- P relayout: C-frag (cols 2tg,2tg+1) -> A-frag (cols tg,tg+4) ----
        unsigned pf[8][4];
        #pragma unroll
        for (int nt = 0; nt < 8; nt++) {
            float t00 = __shfl_sync(full, accs[nt][0], srcA);
            float t01 = __shfl_sync(full, accs[nt][1], srcA);
            float t10 = __shfl_sync(full, accs[nt][0], srcB);
            float t11 = __shfl_sync(full, accs[nt][1], srcB);
            float s00 = __shfl_sync(full, accs[nt][2], srcA);
            float s01 = __shfl_sync(full, accs[nt][3], srcA);
            float s10 = __shfl_sync(full, accs[nt][2], srcB);
            float s11 = __shfl_sync(full, accs[nt][3], srcB);
            const bool odd = (tg & 1);
            pf[nt][0] = cvt_tf32(odd ? t01 : t00);   // P[g][tg]
            pf[nt][1] = cvt_tf32(odd ? s01 : s00);   // P[g+8][tg]
            pf[nt][2] = cvt_tf32(odd ? t11 : t10);   // P[g][tg+4]
            pf[nt][3] = cvt_tf32(odd ? s11 : s10);   // P[g+8][tg+4]
        }

        // ---- O += P V (2-term: p_hi*v_hi + p_hi*v_lo) ----
        #pragma unroll
        for (int kc = 0; kc < 8; kc++) {
            const int kb = kc * 8;
            #pragma unroll
            for (int vt = 0; vt < 4; vt++) {
                unsigned bhi[2], blo[2];
                bhi[0] = __float_as_uint(vsh_hi[(kb + tg) * 40 + vt * 8 + g]);
                bhi[1] = __float_as_uint(vsh_hi[(kb + tg + 4) * 40 + vt * 8 + g]);
                blo[0] = __float_as_uint(vsh_lo[(kb + tg) * 40 + vt * 8 + g]);
                blo[1] = __float_as_uint(vsh_lo[(kb + tg + 4) * 40 + vt * 8 + g]);
                mma_tf32(acco[vt], pf[kc], bhi);
                mma_tf32(acco[vt], pf[kc], blo);
            }
        }
        __syncthreads();
    }

    // ---- epilogue: /S, +x, store ----
    const float inv0 = 1.0f / Srun[0];
    const float inv1 = 1.0f / Srun[1];
    #pragma unroll
    for (int nt = 0; nt < 4; nt++) {
        const int col = nt * 8 + 2 * tg;
        const long a0 = baseqk + (long)row0 * HD + col;
        const long a1 = baseqk + (long)(row0 + 8) * HD + col;
        float2 x0 = *(const float2*)(X + a0);
        float2 x1 = *(const float2*)(X + a1);
        float2 o0 = {acco[nt][0] * inv0 + x0.x, acco[nt][1] * inv0 + x0.y};
        float2 o1 = {acco[nt][2] * inv1 + x1.x, acco[nt][3] * inv1 + x1.y};
        *(float2*)(O + a0) = o0;
        *(float2*)(O + a1) = o1;
    }
}

// ---------------------------------------------------------------------------
// Launch
// ---------------------------------------------------------------------------
extern "C" void kernel_launch(void* const* d_in, const int* in_sizes, int n_in,
                              void* d_out, int out_size)
{
    const float* x     = (const float*)d_in[0];
    const float* scale = (const float*)d_in[1];
    const float* Wq    = (const float*)d_in[2];
    const float* WA    = (const float*)d_in[3];
    const float* W1    = (const float*)d_in[4];
    const float* W2    = (const float*)d_in[5];
    const float* g1    = (const float*)d_in[6];
    const float* g2    = (const float*)d_in[7];
    float* out = (float*)d_out;

    float *xn, *q, *vp, *vr, *res, *hh, *h1, *khi, *klo, *vhi, *vlo;
    cudaGetSymbolAddress((void**)&xn,  g_xn);
    cudaGetSymbolAddress((void**)&q,   g_q);
    cudaGetSymbolAddress((void**)&vp,  g_vp);
    cudaGetSymbolAddress((void**)&vr,  g_vr);
    cudaGetSymbolAddress((void**)&res, g_res);
    cudaGetSymbolAddress((void**)&hh,  g_h);
    cudaGetSymbolAddress((void**)&h1,  g_h1);
    cudaGetSymbolAddress((void**)&khi, g_khi);
    cudaGetSymbolAddress((void**)&klo, g_klo);
    cudaGetSymbolAddress((void**)&vhi, g_vhi);
    cudaGetSymbolAddress((void**)&vlo, g_vlo);

    const int ROWS = BATCH * SEQ;  // 4096
    const int flashSmem = FLASH_SMEM_FLOATS * 4;

    cudaFuncSetAttribute(flash_tc, cudaFuncAttributeMaxDynamicSharedMemorySize,
                         flashSmem);
    cudaFuncSetAttribute(gemm_wq, cudaFuncAttributeMaxDynamicSharedMemorySize,
                         WQ_SMEM_BYTES);
    cudaFuncSetAttribute(gemm_pl<true, 0>,
                         cudaFuncAttributeMaxDynamicSharedMemorySize, GP_SMEM_BYTES);
    cudaFuncSetAttribute(gemm_pl<false, 1>,
                         cudaFuncAttributeMaxDynamicSharedMemorySize, GP_SMEM_BYTES);
    cudaFuncSetAttribute(gemm_pl<false, 2>,
                         cudaFuncAttributeMaxDynamicSharedMemorySize, GP_SMEM_BYTES);

    // 1. xn = rmsnorm(x, g1)
    rmsnorm_kernel<<<ROWS, 256>>>(x, g1, xn);

    // 2. split K (=xn) into tf32 hi/lo (reused by Wq GEMM A-operand AND flash K)
    split_kernel<<<(TOT / 4 + 255) / 256, 256>>>(xn, khi, klo);

    // 3. q = xn @ Wq^T   (compensated 3xTF32, pre-split A)
    gemm_wq<<<dim3(CH / 128, ROWS / 128, 1), 256, WQ_SMEM_BYTES>>>(
        khi, klo, Wq, q, ROWS, CH, CH);

    // 4. gather V'
    gather_v_kernel<<<(TOT + 255) / 256, 256>>>(xn, vp);

    // 5. vr[b] = WA @ vp[b]   (single tf32, pipelined)
    gemm_pl<true, 0><<<dim3(CH / 128, SEQ / 128, BATCH), 256, GP_SMEM_BYTES>>>(
        WA, vp, vr, nullptr, SEQ, CH, SEQ, 0, (long)SEQ * CH, (long)SEQ * CH);

    // 6. split V (=vr) into tf32 hi/lo
    split_kernel<<<(TOT / 4 + 255) / 256, 256>>>(vr, vhi, vlo);

    // 7. attention (+x residual)
    flash_tc<<<dim3(SEQ / 128, HEADS, BATCH), 256, flashSmem>>>(
        q, khi, klo, vhi, vlo, x, scale, res);

    // 8. hh = rmsnorm(res, g2)
    rmsnorm_kernel<<<ROWS, 256>>>(res, g2, hh);

    // 9. h1 = gelu(hh @ W1^T)
    gemm_pl<false, 1><<<dim3(CH / 128, ROWS / 128, 1), 256, GP_SMEM_BYTES>>>(
        hh, W1, h1, nullptr, ROWS, CH, CH, 0, 0, 0);

    // 10. out = h1 @ W2^T + res
    gemm_pl<false, 2><<<dim3(CH / 128, ROWS / 128, 1), 256, GP_SMEM_BYTES>>>(
        h1, W2, out, res, ROWS, CH, CH, 0, 0, 0);
}

// round 8
// speedup vs baseline: 1.9806x; 1.6898x over previous
#include <cuda_runtime.h>
#include <cuda_fp16.h>
#include <math.h>

// ---------------------------------------------------------------------------
// Problem constants
// ---------------------------------------------------------------------------
#define BATCH 2
#define SEQ   2048
#define CH    768
#define HEADS 24
#define HD    32
#define L_PER_B (SEQ * CH)
#define TOT (BATCH * SEQ * CH)

// fp32 scratch
__device__ float g_xn[TOT];
__device__ float g_q[TOT];
__device__ float g_vr[TOT];
__device__ float g_res[TOT];
// half scratch
__device__ __half g_xhi[TOT];
__device__ __half g_xlo[TOT];
__device__ __half g_vpT[TOT];     // [b][c][token]
__device__ __half g_vhiT[TOT];    // [b][c][token]
__device__ __half g_vloT[TOT];
__device__ __half g_hh[TOT];
__device__ __half g_h1[TOT];
__device__ __half g_waH[SEQ * SEQ];
__device__ __half g_wqhi[CH * CH];
__device__ __half g_wqlo[CH * CH];
__device__ __half g_w1H[CH * CH];
__device__ __half g_w2H[CH * CH];

// ---------------------------------------------------------------------------
// helpers
// ---------------------------------------------------------------------------
__device__ __forceinline__ float gelu_exact(float v)
{
    return 0.5f * v * (1.0f + erff(v * 0.7071067811865476f));
}

__device__ __forceinline__ void h_split(float x, __half& hi, __half& lo)
{
    hi = __float2half_rn(x);
    lo = __float2half_rn(x - __half2float(hi));
}

__device__ __forceinline__ unsigned pack_h2(float a, float b)
{
    __half2 h = __floats2half2_rn(a, b);
    return *(unsigned*)&h;
}

__device__ __forceinline__ void mma_f16(float* c, const unsigned* a, const unsigned* b)
{
    asm volatile(
        "mma.sync.aligned.m16n8k16.row.col.f32.f16.f16.f32 "
        "{%0,%1,%2,%3}, {%4,%5,%6,%7}, {%8,%9}, {%0,%1,%2,%3};"
        : "+f"(c[0]), "+f"(c[1]), "+f"(c[2]), "+f"(c[3])
        : "r"(a[0]), "r"(a[1]), "r"(a[2]), "r"(a[3]), "r"(b[0]), "r"(b[1]));
}

__device__ __forceinline__ void cp_async16(void* smem, const void* gmem)
{
    asm volatile("cp.async.cg.shared.global [%0], [%1], 16;"
        :: "r"((unsigned)__cvta_generic_to_shared(smem)), "l"(gmem));
}
#define CP_COMMIT() asm volatile("cp.async.commit_group;")
#define CP_WAIT0()  asm volatile("cp.async.wait_group 0;")
#define CP_WAIT1()  asm volatile("cp.async.wait_group 1;")

// ---------------------------------------------------------------------------
// RMSNorm (optionally half output)
// ---------------------------------------------------------------------------
template<bool HOUT>
__global__ __launch_bounds__(256)
void rmsnorm_kernel(const float* __restrict__ x, const float* __restrict__ g,
                    float* __restrict__ yf, __half* __restrict__ yh)
{
    const int row = blockIdx.x;
    const int t = threadIdx.x;
    const float* xr = x + (long)row * CH;
    float v0 = xr[t], v1 = xr[t + 256], v2 = xr[t + 512];
    float ss = v0 * v0 + v1 * v1 + v2 * v2;

    __shared__ float red[8];
    #pragma unroll
    for (int o = 16; o > 0; o >>= 1) ss += __shfl_xor_sync(0xffffffffu, ss, o);
    if ((t & 31) == 0) red[t >> 5] = ss;
    __syncthreads();
    if (t < 8) {
        float s = red[t];
        #pragma unroll
        for (int o = 4; o > 0; o >>= 1) s += __shfl_xor_sync(0xffu, s, o);
        if (t == 0) red[0] = s;
    }
    __syncthreads();
    const float inv = rsqrtf(red[0] * (1.0f / 768.0f) + 1.1920928955078125e-07f);
    if (HOUT) {
        __half* yr = yh + (long)row * CH;
        yr[t]       = __float2half_rn(v0 * inv * g[t]);
        yr[t + 256] = __float2half_rn(v1 * inv * g[t + 256]);
        yr[t + 512] = __float2half_rn(v2 * inv * g[t + 512]);
    } else {
        float* yr = yf + (long)row * CH;
        yr[t]       = v0 * inv * g[t];
        yr[t + 256] = v1 * inv * g[t + 256];
        yr[t + 512] = v2 * inv * g[t + 512];
    }
}

// ---------------------------------------------------------------------------
// fp32 -> half conversion / hi-lo split (elementwise)
// ---------------------------------------------------------------------------
__global__ __launch_bounds__(256)
void conv_half_kernel(const float* __restrict__ src, __half* __restrict__ dst, long n)
{
    long i = ((long)blockIdx.x * blockDim.x + threadIdx.x) * 4;
    if (i >= n) return;
    float4 v = *(const float4*)(src + i);
    __half2 a = __floats2half2_rn(v.x, v.y);
    __half2 b = __floats2half2_rn(v.z, v.w);
    *(__half2*)(dst + i) = a;
    *(__half2*)(dst + i + 2) = b;
}

__global__ __launch_bounds__(256)
void split_half_kernel(const float* __restrict__ src,
                       __half* __restrict__ hi, __half* __restrict__ lo, long n)
{
    long i = ((long)blockIdx.x * blockDim.x + threadIdx.x) * 4;
    if (i >= n) return;
    float4 v = *(const float4*)(src + i);
    __half h0, l0, h1, l1, h2, l2, h3, l3;
    h_split(v.x, h0, l0); h_split(v.y, h1, l1);
    h_split(v.z, h2, l2); h_split(v.w, h3, l3);
    *(__half2*)(hi + i)     = __halves2half2(h0, h1);
    *(__half2*)(hi + i + 2) = __halves2half2(h2, h3);
    *(__half2*)(lo + i)     = __halves2half2(l0, l1);
    *(__half2*)(lo + i + 2) = __halves2half2(l2, l3);
}

// ---------------------------------------------------------------------------
// Transpose-gather: xn (H,N,HD flat view) -> vpT[b][c][token] (half)
// ---------------------------------------------------------------------------
__global__ __launch_bounds__(256)
void tr_gather_kernel(const float* __restrict__ xn, __half* __restrict__ vpT)
{
    __shared__ float smt[32][33];
    const int b = blockIdx.z, h = blockIdx.y, m0 = blockIdx.x * 32;
    const int tx = threadIdx.x & 31, ty = threadIdx.x >> 5;
    const float* src = xn + (long)b * L_PER_B + (long)h * (SEQ * HD);
    #pragma unroll
    for (int i = 0; i < 4; i++)
        smt[ty + 8 * i][tx] = src[(long)(m0 + ty + 8 * i) * HD + tx];
    __syncthreads();
    __half* dst = vpT + (long)b * L_PER_B;
    #pragma unroll
    for (int i = 0; i < 4; i++) {
        const int d = ty + 8 * i;
        dst[(long)(h * 32 + d) * SEQ + m0 + tx] = __float2half_rn(smt[tx][d]);
    }
}

// ---------------------------------------------------------------------------
// Transpose + split: vr[b][token][c] -> vhiT/vloT [b][c][token] (half)
// ---------------------------------------------------------------------------
__global__ __launch_bounds__(256)
void tr_split_v_kernel(const float* __restrict__ vr,
                       __half* __restrict__ vhiT, __half* __restrict__ vloT)
{
    __shared__ float smt[32][33];
    const int b = blockIdx.z, c0 = blockIdx.y * 32, m0 = blockIdx.x * 32;
    const int tx = threadIdx.x & 31, ty = threadIdx.x >> 5;
    const float* src = vr + (long)b * L_PER_B;
    #pragma unroll
    for (int i = 0; i < 4; i++)
        smt[ty + 8 * i][tx] = src[(long)(m0 + ty + 8 * i) * CH + c0 + tx];
    __syncthreads();
    #pragma unroll
    for (int i = 0; i < 4; i++) {
        const int c = c0 + ty + 8 * i;
        const float v = smt[tx][ty + 8 * i];
        __half hi, lo;
        h_split(v, hi, lo);
        vhiT[(long)b * L_PER_B + (long)c * SEQ + m0 + tx] = hi;
        vloT[(long)b * L_PER_B + (long)c * SEQ + m0 + tx] = lo;
    }
}

// ---------------------------------------------------------------------------
// fp16 NT GEMM: C[m][n] = sum_k A[m][k] * B[n][k], A/B half, 128x128x32 tile.
// EPI: 0 -> fp32 C ; 1 -> exact GELU, half Ch ; 2 -> +R, fp32 C
// Smem: A/B [2][128][40] half = 40960 B total.
// ---------------------------------------------------------------------------
#define GH_BUF 5120   // halfs per matrix per buffer (128*40)
#define GH_SMEM_BYTES (4 * GH_BUF * 2)

template<int EPI>
__global__ __launch_bounds__(256)
void gemm_h(const __half* __restrict__ A, const __half* __restrict__ B,
            float* __restrict__ C, __half* __restrict__ Ch,
            const float* __restrict__ R,
            int M, int N, int K, long sA, long sB, long sC)
{
    extern __shared__ __half smh[];
    __half* Asm = smh;
    __half* Bsm = smh + 2 * GH_BUF;

    A += (long)blockIdx.z * sA;
    B += (long)blockIdx.z * sB;
    if (EPI != 1) C += (long)blockIdx.z * sC;
    if (EPI == 2) R += (long)blockIdx.z * sC;

    const int t = threadIdx.x;
    const int w = t >> 5, lane = t & 31;
    const int g = lane >> 2, tg = lane & 3;
    const int wm = w >> 2, wn = w & 3;
    const int m0 = blockIdx.y * 128, n0 = blockIdx.x * 128;
    const int nk = K >> 5;

    auto stage = [&](int s, int k0) {
        __half* as = Asm + s * GH_BUF;
        __half* bs = Bsm + s * GH_BUF;
        #pragma unroll
        for (int i = 0; i < 2; i++) {
            const int f = t + i * 256;            // 512 16B chunks per matrix
            const int row = f >> 2, seg = f & 3;  // 4 chunks (8 halfs) per row
            cp_async16(&as[row * 40 + seg * 8], A + (long)(m0 + row) * K + k0 + seg * 8);
            cp_async16(&bs[row * 40 + seg * 8], B + (long)(n0 + row) * K + k0 + seg * 8);
        }
    };

    float acc[4][4][4] = {};

    stage(0, 0);
    CP_COMMIT();

    for (int kt = 0; kt < nk; kt++) {
        if (kt + 1 < nk) {
            stage((kt + 1) & 1, (kt + 1) * 32);
            CP_COMMIT();
            CP_WAIT1();
        } else {
            CP_WAIT0();
        }
        __syncthreads();

        const __half* as = Asm + (kt & 1) * GH_BUF;
        const __half* bs = Bsm + (kt & 1) * GH_BUF;

        #pragma unroll
        for (int kc = 0; kc < 2; kc++) {
            const int kb = kc * 16 + 2 * tg;
            unsigned a[4][4], b[4][2];
            #pragma unroll
            for (int mt = 0; mt < 4; mt++) {
                const int mr = wm * 64 + mt * 16 + g;
                a[mt][0] = *(const unsigned*)&as[mr * 40 + kb];
                a[mt][1] = *(const unsigned*)&as[(mr + 8) * 40 + kb];
                a[mt][2] = *(const unsigned*)&as[mr * 40 + kb + 8];
                a[mt][3] = *(const unsigned*)&as[(mr + 8) * 40 + kb + 8];
            }
            #pragma unroll
            for (int nt = 0; nt < 4; nt++) {
                const int nc = wn * 32 + nt * 8 + g;
                b[nt][0] = *(const unsigned*)&bs[nc * 40 + kb];
                b[nt][1] = *(const unsigned*)&bs[nc * 40 + kb + 8];
            }
            #pragma unroll
            for (int mt = 0; mt < 4; mt++)
                #pragma unroll
                for (int nt = 0; nt < 4; nt++)
                    mma_f16(acc[mt][nt], a[mt], b[nt]);
        }
        __syncthreads();
    }

    #pragma unroll
    for (int mt = 0; mt < 4; mt++) {
        #pragma unroll
        for (int nt = 0; nt < 4; nt++) {
            const int row0 = m0 + wm * 64 + mt * 16 + g;
            const int col  = n0 + wn * 32 + nt * 8 + 2 * tg;
            float v0 = acc[mt][nt][0], v1 = acc[mt][nt][1];
            float v2 = acc[mt][nt][2], v3 = acc[mt][nt][3];
            if (EPI == 1) {
                v0 = gelu_exact(v0); v1 = gelu_exact(v1);
                v2 = gelu_exact(v2); v3 = gelu_exact(v3);
                *(__half2*)(Ch + (long)row0 * N + col) = __floats2half2_rn(v0, v1);
                *(__half2*)(Ch + (long)(row0 + 8) * N + col) = __floats2half2_rn(v2, v3);
            } else {
                if (EPI == 2) {
                    float2 r0 = *(const float2*)(R + (long)row0 * N + col);
                    float2 r1 = *(const float2*)(R + (long)(row0 + 8) * N + col);
                    v0 += r0.x; v1 += r0.y; v2 += r1.x; v3 += r1.y;
                }
                float2 o0 = {v0, v1}, o1 = {v2, v3};
                *(float2*)(C + (long)row0 * N + col) = o0;
                *(float2*)(C + (long)(row0 + 8) * N + col) = o1;
            }
        }
    }
}

// ---------------------------------------------------------------------------
// Wq projection: compensated fp16 NT GEMM, pre-split operands.
// acc += Ah*Bh + Ah*Bl + Al*Bh. Smem: 4 matrices x 2 bufs = 81920 B.
// ---------------------------------------------------------------------------
#define WQ_SMEM_BYTES (8 * GH_BUF * 2)

__global__ __launch_bounds__(256)
void gemm_wq(const __half* __restrict__ Ahi, const __half* __restrict__ Alo,
             const __half* __restrict__ Bhi, const __half* __restrict__ Blo,
             float* __restrict__ C, int M, int N, int K)
{
    extern __shared__ __half smw[];
    __half* AH = smw;
    __half* AL = smw + 2 * GH_BUF;
    __half* BH = smw + 4 * GH_BUF;
    __half* BL = smw + 6 * GH_BUF;

    const int t = threadIdx.x;
    const int w = t >> 5, lane = t & 31;
    const int g = lane >> 2, tg = lane & 3;
    const int wm = w >> 2, wn = w & 3;
    const int m0 = blockIdx.y * 128, n0 = blockIdx.x * 128;
    const int nk = K >> 5;

    auto stage = [&](int s, int k0) {
        __half* ah = AH + s * GH_BUF;
        __half* al = AL + s * GH_BUF;
        __half* bh = BH + s * GH_BUF;
        __half* bl = BL + s * GH_BUF;
        #pragma unroll
        for (int i = 0; i < 2; i++) {
            const int f = t + i * 256;
            const int row = f >> 2, seg = f & 3;
            const long asrc = (long)(m0 + row) * K + k0 + seg * 8;
            const long bsrc = (long)(n0 + row) * K + k0 + seg * 8;
            cp_async16(&ah[row * 40 + seg * 8], Ahi + asrc);
            cp_async16(&al[row * 40 + seg * 8], Alo + asrc);
            cp_async16(&bh[row * 40 + seg * 8], Bhi + bsrc);
            cp_async16(&bl[row * 40 + seg * 8], Blo + bsrc);
        }
    };

    float acc[4][4][4] = {};

    stage(0, 0);
    CP_COMMIT();

    for (int kt = 0; kt < nk; kt++) {
        if (kt + 1 < nk) {
            stage((kt + 1) & 1, (kt + 1) * 32);
            CP_COMMIT();
            CP_WAIT1();
        } else {
            CP_WAIT0();
        }
        __syncthreads();

        const __half* ah = AH + (kt & 1) * GH_BUF;
        const __half* al = AL + (kt & 1) * GH_BUF;
        const __half* bh = BH + (kt & 1) * GH_BUF;
        const __half* bl = BL + (kt & 1) * GH_BUF;

        #pragma unroll
        for (int kc = 0; kc < 2; kc++) {
            const int kb = kc * 16 + 2 * tg;
            unsigned aH[4][4], aL[4][4], bHf[4][2], bLf[4][2];
            #pragma unroll
            for (int mt = 0; mt < 4; mt++) {
                const int mr = wm * 64 + mt * 16 + g;
                aH[mt][0] = *(const unsigned*)&ah[mr * 40 + kb];
                aH[mt][1] = *(const unsigned*)&ah[(mr + 8) * 40 + kb];
                aH[mt][2] = *(const unsigned*)&ah[mr * 40 + kb + 8];
                aH[mt][3] = *(const unsigned*)&ah[(mr + 8) * 40 + kb + 8];
                aL[mt][0] = *(const unsigned*)&al[mr * 40 + kb];
                aL[mt][1] = *(const unsigned*)&al[(mr + 8) * 40 + kb];
                aL[mt][2] = *(const unsigned*)&al[mr * 40 + kb + 8];
                aL[mt][3] = *(const unsigned*)&al[(mr + 8) * 40 + kb + 8];
            }
            #pragma unroll
            for (int nt = 0; nt < 4; nt++) {
                const int nc = wn * 32 + nt * 8 + g;
                bHf[nt][0] = *(const unsigned*)&bh[nc * 40 + kb];
                bHf[nt][1] = *(const unsigned*)&bh[nc * 40 + kb + 8];
                bLf[nt][0] = *(const unsigned*)&bl[nc * 40 + kb];
                bLf[nt][1] = *(const unsigned*)&bl[nc * 40 + kb + 8];
            }
            #pragma unroll
            for (int mt = 0; mt < 4; mt++)
                #pragma unroll
                for (int nt = 0; nt < 4; nt++) {
                    mma_f16(acc[mt][nt], aH[mt], bHf[nt]);
                    mma_f16(acc[mt][nt], aH[mt], bLf[nt]);
                    mma_f16(acc[mt][nt], aL[mt], bHf[nt]);
                }
        }
        __syncthreads();
    }

    #pragma unroll
    for (int mt = 0; mt < 4; mt++) {
        #pragma unroll
        for (int nt = 0; nt < 4; nt++) {
            const int row0 = m0 + wm * 64 + mt * 16 + g;
            const int col  = n0 + wn * 32 + nt * 8 + 2 * tg;
            float2 o0 = {acc[mt][nt][0], acc[mt][nt][1]};
            float2 o1 = {acc[mt][nt][2], acc[mt][nt][3]};
            *(float2*)(C + (long)row0 * N + col) = o0;
            *(float2*)(C + (long)(row0 + 8) * N + col) = o1;
        }
    }
}

// ---------------------------------------------------------------------------
// fp16 flash attention.
// QK: hi/lo 3-term fp16 (22-bit logits). PV: fp16 P x (Vhi + Vlo).
// No P relayout needed (fp16 C-frag pair == A-frag pair).
// K smem [key][40] half; V smem [d][72] half (transposed). 38912 B total.
// ---------------------------------------------------------------------------
#define FK_HI(s) ((s) * 2560)
#define FK_LO(s) (5120 + (s) * 2560)
#define FV_HI(s) (10240 + (s) * 2304)
#define FV_LO(s) (14848 + (s) * 2304)
#define FLASH_SMEM_BYTES (19456 * 2)

__global__ __launch_bounds__(256, 2)
void flash_h(const float* __restrict__ Q,
             const __half* __restrict__ Khi, const __half* __restrict__ Klo,
             const __half* __restrict__ VhiT, const __half* __restrict__ VloT,
             const float* __restrict__ X,
             const float* __restrict__ scale_param, float* __restrict__ O)
{
    extern __shared__ __half smf[];

    const int b = blockIdx.z, h = blockIdx.y;
    const int t = threadIdx.x, w = t >> 5, lane = t & 31;
    const int g = lane >> 2, tg = lane & 3;
    const long baseqk = (long)b * L_PER_B + (long)h * (SEQ * HD);
    const long basevT = (long)b * L_PER_B + (long)(h * HD) * SEQ;
    const float coef = logf(768.0f) * scale_param[h] * 5.656854249492381f;

    const int row0 = blockIdx.x * 128 + w * 16 + g;

    auto stage = [&](int s, int kt) {
        __half* kh = smf + FK_HI(s);
        __half* kl = smf + FK_LO(s);
        __half* vh = smf + FV_HI(s);
        __half* vl = smf + FV_LO(s);
        {   // K: 64 rows x 32 halfs = 256 chunks per matrix, 1 per thread
            const int row = t >> 2, seg = t & 3;
            const long src = baseqk + (long)(kt * 64 + row) * HD + seg * 8;
            cp_async16(&kh[row * 40 + seg * 8], Khi + src);
            cp_async16(&kl[row * 40 + seg * 8], Klo + src);
        }
        {   // V^T: 32 d-rows x 64 halfs = 256 chunks per matrix
            const int d = t >> 3, seg = t & 7;
            const long src = basevT + (long)d * SEQ + kt * 64 + seg * 8;
            cp_async16(&vh[d * 72 + seg * 8], VhiT + src);
            cp_async16(&vl[d * 72 + seg * 8], VloT + src);
        }
    };

    // ---- Q fragments (loop-invariant), coef folded, half hi/lo ----
    unsigned qh[2][4], ql[2][4];
    #pragma unroll
    for (int kc = 0; kc < 2; kc++) {
        #pragma unroll
        for (int rr = 0; rr < 2; rr++) {
            const long base = baseqk + (long)(row0 + rr * 8) * HD + kc * 16 + 2 * tg;
            float2 f0 = *(const float2*)(Q + base);
            float2 f1 = *(const float2*)(Q + base + 8);
            float a0 = f0.x * coef, a1 = f0.y * coef;
            float b0 = f1.x * coef, b1 = f1.y * coef;
            __half h0, l0, h1, l1, h2, l2, h3, l3;
            h_split(a0, h0, l0); h_split(a1, h1, l1);
            h_split(b0, h2, l2); h_split(b1, h3, l3);
            __half2 hh0 = __halves2half2(h0, h1), hh1 = __halves2half2(h2, h3);
            __half2 ll0 = __halves2half2(l0, l1), ll1 = __halves2half2(l2, l3);
            qh[kc][rr]     = *(unsigned*)&hh0;
            qh[kc][rr + 2] = *(unsigned*)&hh1;
            ql[kc][rr]     = *(unsigned*)&ll0;
            ql[kc][rr + 2] = *(unsigned*)&ll1;
        }
    }

    float acco[4][4] = {};
    float Mx[2] = {-1e30f, -1e30f};
    float Srun[2] = {0.0f, 0.0f};
    const unsigned full = 0xffffffffu;

    stage(0, 0);
    CP_COMMIT();

    for (int kt = 0; kt < SEQ / 64; kt++) {
        if (kt + 1 < SEQ / 64) {
            stage((kt + 1) & 1, kt + 1);
            CP_COMMIT();
            CP_WAIT1();
        } else {
            CP_WAIT0();
        }
        __syncthreads();

        const int s = kt & 1;
        const __half* ksh_hi = smf + FK_HI(s);
        const __half* ksh_lo = smf + FK_LO(s);
        const __half* vsh_hi = smf + FV_HI(s);
        const __half* vsh_lo = smf + FV_LO(s);

        // ---- S = Q K^T ----
        float accs[8][4] = {};
        #pragma unroll
        for (int nt = 0; nt < 8; nt++) {
            const int key = nt * 8 + g;
            #pragma unroll
            for (int kc = 0; kc < 2; kc++) {
                const int kb = key * 40 + kc * 16 + 2 * tg;
                unsigned bh[2], bl[2];
                bh[0] = *(const unsigned*)&ksh_hi[kb];
                bh[1] = *(const unsigned*)&ksh_hi[kb + 8];
                bl[0] = *(const unsigned*)&ksh_lo[kb];
                bl[1] = *(const unsigned*)&ksh_lo[kb + 8];
                mma_f16(accs[nt], qh[kc], bh);
                mma_f16(accs[nt], qh[kc], bl);
                mma_f16(accs[nt], ql[kc], bh);
            }
        }

        // ---- online softmax; p overwrites accs ----
        #pragma unroll
        for (int rr = 0; rr < 2; rr++) {
            const int i0 = rr * 2, i1 = rr * 2 + 1;
            float m = accs[0][i0];
            #pragma unroll
            for (int nt = 0; nt < 8; nt++) {
                m = fmaxf(m, accs[nt][i0]);
                m = fmaxf(m, accs[nt][i1]);
            }
            m = fmaxf(m, __shfl_xor_sync(full, m, 1));
            m = fmaxf(m, __shfl_xor_sync(full, m, 2));
            const float Mn = fmaxf(Mx[rr], m);
            const float corr = __expf(Mx[rr] - Mn);
            Srun[rr] *= corr;
            #pragma unroll
            for (int nt = 0; nt < 4; nt++) {
                acco[nt][i0] *= corr;
                acco[nt][i1] *= corr;
            }
            Mx[rr] = Mn;
            float lsum = 0.0f;
            #pragma unroll
            for (int nt = 0; nt < 8; nt++) {
                const float p0 = __expf(accs[nt][i0] - Mn);
                const float p1 = __expf(accs[nt][i1] - Mn);
                lsum += p0 + p1;
                accs[nt][i0] = p0;
                accs[nt][i1] = p1;
            }
            lsum += __shfl_xor_sync(full, lsum, 1);
            lsum += __shfl_xor_sync(full, lsum, 2);
            Srun[rr] += lsum;
        }

        // ---- pack P to fp16 A-fragments (identity layout, no shuffles) ----
        unsigned ph[8][2];
        #pragma unroll
        for (int nt = 0; nt < 8; nt++) {
            ph[nt][0] = pack_h2(accs[nt][0], accs[nt][1]);
            ph[nt][1] = pack_h2(accs[nt][2], accs[nt][3]);
        }

        // ---- O += P V ----
        #pragma unroll
        for (int kcK = 0; kcK < 4; kcK++) {
            unsigned pa[4] = {ph[2 * kcK][0], ph[2 * kcK][1],
                              ph[2 * kcK + 1][0], ph[2 * kcK + 1][1]};
            #pragma unroll
            for (int vt = 0; vt < 4; vt++) {
                const int vb = (vt * 8 + g) * 72 + kcK * 16 + 2 * tg;
                unsigned bh[2], bl[2];
                bh[0] = *(const unsigned*)&vsh_hi[vb];
                bh[1] = *(const unsigned*)&vsh_hi[vb + 8];
                bl[0] = *(const unsigned*)&vsh_lo[vb];
                bl[1] = *(const unsigned*)&vsh_lo[vb + 8];
                mma_f16(acco[vt], pa, bh);
                mma_f16(acco[vt], pa, bl);
            }
        }
        __syncthreads();
    }

    // ---- epilogue: /S, +x, store ----
    const float inv0 = 1.0f / Srun[0];
    const float inv1 = 1.0f / Srun[1];
    #pragma unroll
    for (int nt = 0; nt < 4; nt++) {
        const int col = nt * 8 + 2 * tg;
        const long a0 = baseqk + (long)row0 * HD + col;
        const long a1 = baseqk + (long)(row0 + 8) * HD + col;
        float2 x0 = *(const float2*)(X + a0);
        float2 x1 = *(const float2*)(X + a1);
        float2 o0 = {acco[nt][0] * inv0 + x0.x, acco[nt][1] * inv0 + x0.y};
        float2 o1 = {acco[nt][2] * inv1 + x1.x, acco[nt][3] * inv1 + x1.y};
        *(float2*)(O + a0) = o0;
        *(float2*)(O + a1) = o1;
    }
}

// ---------------------------------------------------------------------------
// Launch
// ---------------------------------------------------------------------------
extern "C" void kernel_launch(void* const* d_in, const int* in_sizes, int n_in,
                              void* d_out, int out_size)
{
    const float* x     = (const float*)d_in[0];
    const float* scale = (const float*)d_in[1];
    const float* Wq    = (const float*)d_in[2];
    const float* WA    = (const float*)d_in[3];
    const float* W1    = (const float*)d_in[4];
    const float* W2    = (const float*)d_in[5];
    const float* g1    = (const float*)d_in[6];
    const float* g2    = (const float*)d_in[7];
    float* out = (float*)d_out;

    float *xn, *q, *vr, *res;
    __half *xhi, *xlo, *vpT, *vhiT, *vloT, *hh, *h1;
    __half *waH, *wqhi, *wqlo, *w1H, *w2H;
    cudaGetSymbolAddress((void**)&xn,   g_xn);
    cudaGetSymbolAddress((void**)&q,    g_q);
    cudaGetSymbolAddress((void**)&vr,   g_vr);
    cudaGetSymbolAddress((void**)&res,  g_res);
    cudaGetSymbolAddress((void**)&xhi,  g_xhi);
    cudaGetSymbolAddress((void**)&xlo,  g_xlo);
    cudaGetSymbolAddress((void**)&vpT,  g_vpT);
    cudaGetSymbolAddress((void**)&vhiT, g_vhiT);
    cudaGetSymbolAddress((void**)&vloT, g_vloT);
    cudaGetSymbolAddress((void**)&hh,   g_hh);
    cudaGetSymbolAddress((void**)&h1,   g_h1);
    cudaGetSymbolAddress((void**)&waH,  g_waH);
    cudaGetSymbolAddress((void**)&wqhi, g_wqhi);
    cudaGetSymbolAddress((void**)&wqlo, g_wqlo);
    cudaGetSymbolAddress((void**)&w1H,  g_w1H);
    cudaGetSymbolAddress((void**)&w2H,  g_w2H);

    const int ROWS = BATCH * SEQ;  // 4096

    cudaFuncSetAttribute(gemm_wq, cudaFuncAttributeMaxDynamicSharedMemorySize,
                         WQ_SMEM_BYTES);
    cudaFuncSetAttribute(flash_h, cudaFuncAttributeMaxDynamicSharedMemorySize,
                         FLASH_SMEM_BYTES);
    cudaFuncSetAttribute(gemm_h<0>, cudaFuncAttributeMaxDynamicSharedMemorySize,
                         GH_SMEM_BYTES);
    cudaFuncSetAttribute(gemm_h<1>, cudaFuncAttributeMaxDynamicSharedMemorySize,
                         GH_SMEM_BYTES);
    cudaFuncSetAttribute(gemm_h<2>, cudaFuncAttributeMaxDynamicSharedMemorySize,
                         GH_SMEM_BYTES);

    // --- weight conversions (cheap, every launch, deterministic) ---
    conv_half_kernel<<<(SEQ * SEQ / 4 + 255) / 256, 256>>>(WA, waH, (long)SEQ * SEQ);
    conv_half_kernel<<<(CH * CH / 4 + 255) / 256, 256>>>(W1, w1H, (long)CH * CH);
    conv_half_kernel<<<(CH * CH / 4 + 255) / 256, 256>>>(W2, w2H, (long)CH * CH);
    split_half_kernel<<<(CH * CH / 4 + 255) / 256, 256>>>(Wq, wqhi, wqlo, (long)CH * CH);

    // 1. xn = rmsnorm(x, g1)
    rmsnorm_kernel<false><<<ROWS, 256>>>(x, g1, xn, nullptr);

    // 2. split xn -> half hi/lo (Wq A-operand AND flash K)
    split_half_kernel<<<(TOT / 4 + 255) / 256, 256>>>(xn, xhi, xlo, (long)TOT);

    // 3. q = xn @ Wq^T  (compensated fp16, fp32-grade logits)
    gemm_wq<<<dim3(CH / 128, ROWS / 128, 1), 256, WQ_SMEM_BYTES>>>(
        xhi, xlo, wqhi, wqlo, q, ROWS, CH, CH);

    // 4. transpose-gather V' -> vpT[b][c][token] (half)
    tr_gather_kernel<<<dim3(SEQ / 32, HEADS, BATCH), 256>>>(xn, vpT);

    // 5. vr[b] = WA @ vp[b]  == NT(waH, vpT)
    gemm_h<0><<<dim3(CH / 128, SEQ / 128, BATCH), 256, GH_SMEM_BYTES>>>(
        waH, vpT, vr, nullptr, nullptr, SEQ, CH, SEQ,
        0, (long)CH * SEQ, (long)SEQ * CH);

    // 6. transpose + split vr -> vhiT/vloT [b][c][token]
    tr_split_v_kernel<<<dim3(SEQ / 32, CH / 32, BATCH), 256>>>(vr, vhiT, vloT);

    // 7. attention (+x residual)
    flash_h<<<dim3(SEQ / 128, HEADS, BATCH), 256, FLASH_SMEM_BYTES>>>(
        q, xhi, xlo, vhiT, vloT, x, scale, res);

    // 8. hh = rmsnorm(res, g2) -> half
    rmsnorm_kernel<true><<<ROWS, 256>>>(res, g2, nullptr, hh);

    // 9. h1 = gelu(hh @ W1^T) -> half
    gemm_h<1><<<dim3(CH / 128, ROWS / 128, 1), 256, GH_SMEM_BYTES>>>(
        hh, w1H, nullptr, h1, nullptr, ROWS, CH, CH, 0, 0, 0);

    // 10. out = h1 @ W2^T + res
    gemm_h<2><<<dim3(CH / 128, ROWS / 128, 1), 256, GH_SMEM_BYTES>>>(
        h1, w2H, out, nullptr, res, ROWS, CH, CH, 0, 0, 0);
}

// round 9
// speedup vs baseline: 2.1301x; 1.0755x over previous
#include <cuda_runtime.h>
#include <cuda_fp16.h>
#include <math.h>

// ---------------------------------------------------------------------------
// Problem constants
// ---------------------------------------------------------------------------
#define BATCH 2
#define SEQ   2048
#define CH    768
#define HEADS 24
#define HD    32
#define L_PER_B (SEQ * CH)
#define TOT (BATCH * SEQ * CH)

// fp32 scratch
__device__ float g_q[TOT];
__device__ float g_vr[TOT];
__device__ float g_res[TOT];
// half scratch
__device__ __half g_xhi[TOT];
__device__ __half g_xlo[TOT];
__device__ __half g_vpT[TOT];     // [b][c][token]
__device__ __half g_vT[TOT];      // [b][c][token]
__device__ __half g_hh[TOT];
__device__ __half g_h1[TOT];
__device__ __half g_waH[SEQ * SEQ];
__device__ __half g_wqhi[CH * CH];
__device__ __half g_wqlo[CH * CH];
__device__ __half g_w1H[CH * CH];
__device__ __half g_w2H[CH * CH];

// ---------------------------------------------------------------------------
// helpers
// ---------------------------------------------------------------------------
__device__ __forceinline__ float gelu_exact(float v)
{
    return 0.5f * v * (1.0f + erff(v * 0.7071067811865476f));
}

__device__ __forceinline__ void h_split(float x, __half& hi, __half& lo)
{
    hi = __float2half_rn(x);
    lo = __float2half_rn(x - __half2float(hi));
}

__device__ __forceinline__ unsigned pack_h2(float a, float b)
{
    __half2 h = __floats2half2_rn(a, b);
    return *(unsigned*)&h;
}

__device__ __forceinline__ void mma_f16(float* c, const unsigned* a, const unsigned* b)
{
    asm volatile(
        "mma.sync.aligned.m16n8k16.row.col.f32.f16.f16.f32 "
        "{%0,%1,%2,%3}, {%4,%5,%6,%7}, {%8,%9}, {%0,%1,%2,%3};"
        : "+f"(c[0]), "+f"(c[1]), "+f"(c[2]), "+f"(c[3])
        : "r"(a[0]), "r"(a[1]), "r"(a[2]), "r"(a[3]), "r"(b[0]), "r"(b[1]));
}

__device__ __forceinline__ void cp_async16(void* smem, const void* gmem)
{
    asm volatile("cp.async.cg.shared.global [%0], [%1], 16;"
        :: "r"((unsigned)__cvta_generic_to_shared(smem)), "l"(gmem));
}
#define CP_COMMIT() asm volatile("cp.async.commit_group;")
#define CP_WAIT0()  asm volatile("cp.async.wait_group 0;")
#define CP_WAIT1()  asm volatile("cp.async.wait_group 1;")

// ---------------------------------------------------------------------------
// RMSNorm variants
// ---------------------------------------------------------------------------
__device__ __forceinline__ float rms_inv(float v0, float v1, float v2, int t)
{
    float ss = v0 * v0 + v1 * v1 + v2 * v2;
    __shared__ float red[8];
    #pragma unroll
    for (int o = 16; o > 0; o >>= 1) ss += __shfl_xor_sync(0xffffffffu, ss, o);
    if ((t & 31) == 0) red[t >> 5] = ss;
    __syncthreads();
    if (t < 8) {
        float s = red[t];
        #pragma unroll
        for (int o = 4; o > 0; o >>= 1) s += __shfl_xor_sync(0xffu, s, o);
        if (t == 0) red[0] = s;
    }
    __syncthreads();
    return rsqrtf(red[0] * (1.0f / 768.0f) + 1.1920928955078125e-07f);
}

// rmsnorm -> half hi/lo split output
__global__ __launch_bounds__(256)
void rmsnorm_split_kernel(const float* __restrict__ x, const float* __restrict__ g,
                          __half* __restrict__ hi, __half* __restrict__ lo)
{
    const int row = blockIdx.x;
    const int t = threadIdx.x;
    const float* xr = x + (long)row * CH;
    float v0 = xr[t], v1 = xr[t + 256], v2 = xr[t + 512];
    const float inv = rms_inv(v0, v1, v2, t);
    __half h, l;
    h_split(v0 * inv * g[t], h, l);
    hi[(long)row * CH + t] = h; lo[(long)row * CH + t] = l;
    h_split(v1 * inv * g[t + 256], h, l);
    hi[(long)row * CH + t + 256] = h; lo[(long)row * CH + t + 256] = l;
    h_split(v2 * inv * g[t + 512], h, l);
    hi[(long)row * CH + t + 512] = h; lo[(long)row * CH + t + 512] = l;
}

// rmsnorm -> half output
__global__ __launch_bounds__(256)
void rmsnorm_h_kernel(const float* __restrict__ x, const float* __restrict__ g,
                      __half* __restrict__ y)
{
    const int row = blockIdx.x;
    const int t = threadIdx.x;
    const float* xr = x + (long)row * CH;
    float v0 = xr[t], v1 = xr[t + 256], v2 = xr[t + 512];
    const float inv = rms_inv(v0, v1, v2, t);
    __half* yr = y + (long)row * CH;
    yr[t]       = __float2half_rn(v0 * inv * g[t]);
    yr[t + 256] = __float2half_rn(v1 * inv * g[t + 256]);
    yr[t + 512] = __float2half_rn(v2 * inv * g[t + 512]);
}

// ---------------------------------------------------------------------------
// Fused weight prep: WA/W1/W2 -> half ; Wq -> hi/lo split. One launch.
// Index space in float4 units.
// ---------------------------------------------------------------------------
#define N_WA (SEQ * SEQ / 4)
#define N_W  (CH * CH / 4)

__global__ __launch_bounds__(256)
void weight_prep_kernel(const float* __restrict__ WA, const float* __restrict__ W1,
                        const float* __restrict__ W2, const float* __restrict__ Wq,
                        __half* __restrict__ waH, __half* __restrict__ w1H,
                        __half* __restrict__ w2H,
                        __half* __restrict__ wqhi, __half* __restrict__ wqlo)
{
    long i = (long)blockIdx.x * blockDim.x + threadIdx.x;
    const float* src;
    __half* dst;
    if (i < N_WA) { src = WA; dst = waH; }
    else if ((i -= N_WA) < N_W) { src = W1; dst = w1H; }
    else if ((i -= N_W) < N_W)  { src = W2; dst = w2H; }
    else if ((i -= N_W) < N_W) {
        const long e = i * 4;
        float4 v = *(const float4*)(Wq + e);
        __half h0, l0, h1, l1, h2, l2, h3, l3;
        h_split(v.x, h0, l0); h_split(v.y, h1, l1);
        h_split(v.z, h2, l2); h_split(v.w, h3, l3);
        *(__half2*)(wqhi + e)     = __halves2half2(h0, h1);
        *(__half2*)(wqhi + e + 2) = __halves2half2(h2, h3);
        *(__half2*)(wqlo + e)     = __halves2half2(l0, l1);
        *(__half2*)(wqlo + e + 2) = __halves2half2(l2, l3);
        return;
    } else return;
    const long e = i * 4;
    float4 v = *(const float4*)(src + e);
    *(__half2*)(dst + e)     = __floats2half2_rn(v.x, v.y);
    *(__half2*)(dst + e + 2) = __floats2half2_rn(v.z, v.w);
}

// ---------------------------------------------------------------------------
// Transpose-gather: xhi (H,N,HD flat view, half) -> vpT[b][c][token] (half)
// ---------------------------------------------------------------------------
__global__ __launch_bounds__(256)
void tr_gather_kernel(const __half* __restrict__ xhi, __half* __restrict__ vpT)
{
    __shared__ __half smt[32][34];
    const int b = blockIdx.z, h = blockIdx.y, m0 = blockIdx.x * 32;
    const int tx = threadIdx.x & 31, ty = threadIdx.x >> 5;
    const __half* src = xhi + (long)b * L_PER_B + (long)h * (SEQ * HD);
    #pragma unroll
    for (int i = 0; i < 4; i++)
        smt[ty + 8 * i][tx] = src[(long)(m0 + ty + 8 * i) * HD + tx];
    __syncthreads();
    __half* dst = vpT + (long)b * L_PER_B;
    #pragma unroll
    for (int i = 0; i < 4; i++) {
        const int d = ty + 8 * i;
        dst[(long)(h * 32 + d) * SEQ + m0 + tx] = smt[tx][d];
    }
}

// ---------------------------------------------------------------------------
// Transpose V: vr[b][token][c] (fp32) -> vT[b][c][token] (half)
// ---------------------------------------------------------------------------
__global__ __launch_bounds__(256)
void tr_v_kernel(const float* __restrict__ vr, __half* __restrict__ vT)
{
    __shared__ float smt[32][33];
    const int b = blockIdx.z, c0 = blockIdx.y * 32, m0 = blockIdx.x * 32;
    const int tx = threadIdx.x & 31, ty = threadIdx.x >> 5;
    const float* src = vr + (long)b * L_PER_B;
    #pragma unroll
    for (int i = 0; i < 4; i++)
        smt[ty + 8 * i][tx] = src[(long)(m0 + ty + 8 * i) * CH + c0 + tx];
    __syncthreads();
    #pragma unroll
    for (int i = 0; i < 4; i++) {
        const int c = c0 + ty + 8 * i;
        vT[(long)b * L_PER_B + (long)c * SEQ + m0 + tx] =
            __float2half_rn(smt[tx][ty + 8 * i]);
    }
}

// ---------------------------------------------------------------------------
// fp16 NT GEMM: C[m][n] = sum_k A[m][k] * B[n][k], 128x128x32 tile.
// EPI: 0 -> fp32 C ; 1 -> exact GELU, half Ch ; 2 -> +R, fp32 C
// ---------------------------------------------------------------------------
#define GH_BUF 5120
#define GH_SMEM_BYTES (4 * GH_BUF * 2)

template<int EPI>
__global__ __launch_bounds__(256)
void gemm_h(const __half* __restrict__ A, const __half* __restrict__ B,
            float* __restrict__ C, __half* __restrict__ Ch,
            const float* __restrict__ R,
            int M, int N, int K, long sA, long sB, long sC)
{
    extern __shared__ __half smh[];
    __half* Asm = smh;
    __half* Bsm = smh + 2 * GH_BUF;

    A += (long)blockIdx.z * sA;
    B += (long)blockIdx.z * sB;
    if (EPI != 1) C += (long)blockIdx.z * sC;
    if (EPI == 2) R += (long)blockIdx.z * sC;

    const int t = threadIdx.x;
    const int w = t >> 5, lane = t & 31;
    const int g = lane >> 2, tg = lane & 3;
    const int wm = w >> 2, wn = w & 3;
    const int m0 = blockIdx.y * 128, n0 = blockIdx.x * 128;
    const int nk = K >> 5;

    auto stage = [&](int s, int k0) {
        __half* as = Asm + s * GH_BUF;
        __half* bs = Bsm + s * GH_BUF;
        #pragma unroll
        for (int i = 0; i < 2; i++) {
            const int f = t + i * 256;
            const int row = f >> 2, seg = f & 3;
            cp_async16(&as[row * 40 + seg * 8], A + (long)(m0 + row) * K + k0 + seg * 8);
            cp_async16(&bs[row * 40 + seg * 8], B + (long)(n0 + row) * K + k0 + seg * 8);
        }
    };

    float acc[4][4][4] = {};

    stage(0, 0);
    CP_COMMIT();

    for (int kt = 0; kt < nk; kt++) {
        if (kt + 1 < nk) {
            stage((kt + 1) & 1, (kt + 1) * 32);
            CP_COMMIT();
            CP_WAIT1();
        } else {
            CP_WAIT0();
        }
        __syncthreads();

        const __half* as = Asm + (kt & 1) * GH_BUF;
        const __half* bs = Bsm + (kt & 1) * GH_BUF;

        #pragma unroll
        for (int kc = 0; kc < 2; kc++) {
            const int kb = kc * 16 + 2 * tg;
            unsigned a[4][4], b[4][2];
            #pragma unroll
            for (int mt = 0; mt < 4; mt++) {
                const int mr = wm * 64 + mt * 16 + g;
                a[mt][0] = *(const unsigned*)&as[mr * 40 + kb];
                a[mt][1] = *(const unsigned*)&as[(mr + 8) * 40 + kb];
                a[mt][2] = *(const unsigned*)&as[mr * 40 + kb + 8];
                a[mt][3] = *(const unsigned*)&as[(mr + 8) * 40 + kb + 8];
            }
            #pragma unroll
            for (int nt = 0; nt < 4; nt++) {
                const int nc = wn * 32 + nt * 8 + g;
                b[nt][0] = *(const unsigned*)&bs[nc * 40 + kb];
                b[nt][1] = *(const unsigned*)&bs[nc * 40 + kb + 8];
            }
            #pragma unroll
            for (int mt = 0; mt < 4; mt++)
                #pragma unroll
                for (int nt = 0; nt < 4; nt++)
                    mma_f16(acc[mt][nt], a[mt], b[nt]);
        }
        __syncthreads();
    }

    #pragma unroll
    for (int mt = 0; mt < 4; mt++) {
        #pragma unroll
        for (int nt = 0; nt < 4; nt++) {
            const int row0 = m0 + wm * 64 + mt * 16 + g;
            const int col  = n0 + wn * 32 + nt * 8 + 2 * tg;
            float v0 = acc[mt][nt][0], v1 = acc[mt][nt][1];
            float v2 = acc[mt][nt][2], v3 = acc[mt][nt][3];
            if (EPI == 1) {
                v0 = gelu_exact(v0); v1 = gelu_exact(v1);
                v2 = gelu_exact(v2); v3 = gelu_exact(v3);
                *(__half2*)(Ch + (long)row0 * N + col) = __floats2half2_rn(v0, v1);
                *(__half2*)(Ch + (long)(row0 + 8) * N + col) = __floats2half2_rn(v2, v3);
            } else {
                if (EPI == 2) {
                    float2 r0 = *(const float2*)(R + (long)row0 * N + col);
                    float2 r1 = *(const float2*)(R + (long)(row0 + 8) * N + col);
                    v0 += r0.x; v1 += r0.y; v2 += r1.x; v3 += r1.y;
                }
                float2 o0 = {v0, v1}, o1 = {v2, v3};
                *(float2*)(C + (long)row0 * N + col) = o0;
                *(float2*)(C + (long)(row0 + 8) * N + col) = o1;
            }
        }
    }
}

// ---------------------------------------------------------------------------
// Wq projection: compensated fp16 NT GEMM, pre-split operands.
// ---------------------------------------------------------------------------
#define WQ_SMEM_BYTES (8 * GH_BUF * 2)

__global__ __launch_bounds__(256)
void gemm_wq(const __half* __restrict__ Ahi, const __half* __restrict__ Alo,
             const __half* __restrict__ Bhi, const __half* __restrict__ Blo,
             float* __restrict__ C, int M, int N, int K)
{
    extern __shared__ __half smw[];
    __half* AH = smw;
    __half* AL = smw + 2 * GH_BUF;
    __half* BH = smw + 4 * GH_BUF;
    __half* BL = smw + 6 * GH_BUF;

    const int t = threadIdx.x;
    const int w = t >> 5, lane = t & 31;
    const int g = lane >> 2, tg = lane & 3;
    const int wm = w >> 2, wn = w & 3;
    const int m0 = blockIdx.y * 128, n0 = blockIdx.x * 128;
    const int nk = K >> 5;

    auto stage = [&](int s, int k0) {
        __half* ah = AH + s * GH_BUF;
        __half* al = AL + s * GH_BUF;
        __half* bh = BH + s * GH_BUF;
        __half* bl = BL + s * GH_BUF;
        #pragma unroll
        for (int i = 0; i < 2; i++) {
            const int f = t + i * 256;
            const int row = f >> 2, seg = f & 3;
            const long asrc = (long)(m0 + row) * K + k0 + seg * 8;
            const long bsrc = (long)(n0 + row) * K + k0 + seg * 8;
            cp_async16(&ah[row * 40 + seg * 8], Ahi + asrc);
            cp_async16(&al[row * 40 + seg * 8], Alo + asrc);
            cp_async16(&bh[row * 40 + seg * 8], Bhi + bsrc);
            cp_async16(&bl[row * 40 + seg * 8], Blo + bsrc);
        }
    };

    float acc[4][4][4] = {};

    stage(0, 0);
    CP_COMMIT();

    for (int kt = 0; kt < nk; kt++) {
        if (kt + 1 < nk) {
            stage((kt + 1) & 1, (kt + 1) * 32);
            CP_COMMIT();
            CP_WAIT1();
        } else {
            CP_WAIT0();
        }
        __syncthreads();

        const __half* ah = AH + (kt & 1) * GH_BUF;
        const __half* al = AL + (kt & 1) * GH_BUF;
        const __half* bh = BH + (kt & 1) * GH_BUF;
        const __half* bl = BL + (kt & 1) * GH_BUF;

        #pragma unroll
        for (int kc = 0; kc < 2; kc++) {
            const int kb = kc * 16 + 2 * tg;
            unsigned aH[4][4], aL[4][4], bHf[4][2], bLf[4][2];
            #pragma unroll
            for (int mt = 0; mt < 4; mt++) {
                const int mr = wm * 64 + mt * 16 + g;
                aH[mt][0] = *(const unsigned*)&ah[mr * 40 + kb];
                aH[mt][1] = *(const unsigned*)&ah[(mr + 8) * 40 + kb];
                aH[mt][2] = *(const unsigned*)&ah[mr * 40 + kb + 8];
                aH[mt][3] = *(const unsigned*)&ah[(mr + 8) * 40 + kb + 8];
                aL[mt][0] = *(const unsigned*)&al[mr * 40 + kb];
                aL[mt][1] = *(const unsigned*)&al[(mr + 8) * 40 + kb];
                aL[mt][2] = *(const unsigned*)&al[mr * 40 + kb + 8];
                aL[mt][3] = *(const unsigned*)&al[(mr + 8) * 40 + kb + 8];
            }
            #pragma unroll
            for (int nt = 0; nt < 4; nt++) {
                const int nc = wn * 32 + nt * 8 + g;
                bHf[nt][0] = *(const unsigned*)&bh[nc * 40 + kb];
                bHf[nt][1] = *(const unsigned*)&bh[nc * 40 + kb + 8];
                bLf[nt][0] = *(const unsigned*)&bl[nc * 40 + kb];
                bLf[nt][1] = *(const unsigned*)&bl[nc * 40 + kb + 8];
            }
            #pragma unroll
            for (int mt = 0; mt < 4; mt++)
                #pragma unroll
                for (int nt = 0; nt < 4; nt++) {
                    mma_f16(acc[mt][nt], aH[mt], bHf[nt]);
                    mma_f16(acc[mt][nt], aH[mt], bLf[nt]);
                    mma_f16(acc[mt][nt], aL[mt], bHf[nt]);
                }
        }
        __syncthreads();
    }

    #pragma unroll
    for (int mt = 0; mt < 4; mt++) {
        #pragma unroll
        for (int nt = 0; nt < 4; nt++) {
            const int row0 = m0 + wm * 64 + mt * 16 + g;
            const int col  = n0 + wn * 32 + nt * 8 + 2 * tg;
            float2 o0 = {acc[mt][nt][0], acc[mt][nt][1]};
            float2 o1 = {acc[mt][nt][2], acc[mt][nt][3]};
            *(float2*)(C + (long)row0 * N + col) = o0;
            *(float2*)(C + (long)(row0 + 8) * N + col) = o1;
        }
    }
}

// ---------------------------------------------------------------------------
// fp16 flash attention.
// QK: hi/lo 3-term fp16 (22-bit logits). PV: single fp16 (V rounding benign:
// attn err ~ 2^-12*sqrt(sum p^2) << 1e-4 since sum p = 1).
// K smem [key][40] half hi/lo; V^T smem [d][72] half. 50176 B total.
// ---------------------------------------------------------------------------
#define FK_HI(s) ((s) * 2560)
#define FK_LO(s) (5120 + (s) * 2560)
#define FV(s)    (10240 + (s) * 2304)
#define FLASH_SMEM_BYTES (12544 * 4)

__global__ __launch_bounds__(256, 2)
void flash_h(const float* __restrict__ Q,
             const __half* __restrict__ Khi, const __half* __restrict__ Klo,
             const __half* __restrict__ VT,
             const float* __restrict__ X,
             const float* __restrict__ scale_param, float* __restrict__ O)
{
    extern __shared__ __half smf[];

    const int b = blockIdx.z, h = blockIdx.y;
    const int t = threadIdx.x, w = t >> 5, lane = t & 31;
    const int g = lane >> 2, tg = lane & 3;
    const long baseqk = (long)b * L_PER_B + (long)h * (SEQ * HD);
    const long basevT = (long)b * L_PER_B + (long)(h * HD) * SEQ;
    const float coef = logf(768.0f) * scale_param[h] * 5.656854249492381f;

    const int row0 = blockIdx.x * 128 + w * 16 + g;

    auto stage = [&](int s, int kt) {
        __half* kh = smf + FK_HI(s);
        __half* kl = smf + FK_LO(s);
        __half* vh = smf + FV(s);
        {   // K: 64 rows x 32 halfs = 256 chunks per matrix
            const int row = t >> 2, seg = t & 3;
            const long src = baseqk + (long)(kt * 64 + row) * HD + seg * 8;
            cp_async16(&kh[row * 40 + seg * 8], Khi + src);
            cp_async16(&kl[row * 40 + seg * 8], Klo + src);
        }
        {   // V^T: 32 d-rows x 64 halfs = 256 chunks
            const int d = t >> 3, seg = t & 7;
            const long src = basevT + (long)d * SEQ + kt * 64 + seg * 8;
            cp_async16(&vh[d * 72 + seg * 8], VT + src);
        }
    };

    // ---- Q fragments (loop-invariant), coef folded, half hi/lo ----
    unsigned qh[2][4], ql[2][4];
    #pragma unroll
    for (int kc = 0; kc < 2; kc++) {
        #pragma unroll
        for (int rr = 0; rr < 2; rr++) {
            const long base = baseqk + (long)(row0 + rr * 8) * HD + kc * 16 + 2 * tg;
            float2 f0 = *(const float2*)(Q + base);
            float2 f1 = *(const float2*)(Q + base + 8);
            float a0 = f0.x * coef, a1 = f0.y * coef;
            float b0 = f1.x * coef, b1 = f1.y * coef;
            __half h0, l0, h1, l1, h2, l2, h3, l3;
            h_split(a0, h0, l0); h_split(a1, h1, l1);
            h_split(b0, h2, l2); h_split(b1, h3, l3);
            __half2 hh0 = __halves2half2(h0, h1), hh1 = __halves2half2(h2, h3);
            __half2 ll0 = __halves2half2(l0, l1), ll1 = __halves2half2(l2, l3);
            qh[kc][rr]     = *(unsigned*)&hh0;
            qh[kc][rr + 2] = *(unsigned*)&hh1;
            ql[kc][rr]     = *(unsigned*)&ll0;
            ql[kc][rr + 2] = *(unsigned*)&ll1;
        }
    }

    float acco[4][4] = {};
    float Mx[2] = {-1e30f, -1e30f};
    float Srun[2] = {0.0f, 0.0f};
    const unsigned full = 0xffffffffu;

    stage(0, 0);
    CP_COMMIT();

    for (int kt = 0; kt < SEQ / 64; kt++) {
        if (kt + 1 < SEQ / 64) {
            stage((kt + 1) & 1, kt + 1);
            CP_COMMIT();
            CP_WAIT1();
        } else {
            CP_WAIT0();
        }
        __syncthreads();

        const int s = kt & 1;
        const __half* ksh_hi = smf + FK_HI(s);
        const __half* ksh_lo = smf + FK_LO(s);
        const __half* vsh = smf + FV(s);

        // ---- S = Q K^T ----
        float accs[8][4] = {};
        #pragma unroll
        for (int nt = 0; nt < 8; nt++) {
            const int key = nt * 8 + g;
            #pragma unroll
            for (int kc = 0; kc < 2; kc++) {
                const int kb = key * 40 + kc * 16 + 2 * tg;
                unsigned bh[2], bl[2];
                bh[0] = *(const unsigned*)&ksh_hi[kb];
                bh[1] = *(const unsigned*)&ksh_hi[kb + 8];
                bl[0] = *(const unsigned*)&ksh_lo[kb];
                bl[1] = *(const unsigned*)&ksh_lo[kb + 8];
                mma_f16(accs[nt], qh[kc], bh);
                mma_f16(accs[nt], qh[kc], bl);
                mma_f16(accs[nt], ql[kc], bh);
            }
        }

        // ---- online softmax; p overwrites accs ----
        #pragma unroll
        for (int rr = 0; rr < 2; rr++) {
            const int i0 = rr * 2, i1 = rr * 2 + 1;
            float m = accs[0][i0];
            #pragma unroll
            for (int nt = 0; nt < 8; nt++) {
                m = fmaxf(m, accs[nt][i0]);
                m = fmaxf(m, accs[nt][i1]);
            }
            m = fmaxf(m, __shfl_xor_sync(full, m, 1));
            m = fmaxf(m, __shfl_xor_sync(full, m, 2));
            const float Mn = fmaxf(Mx[rr], m);
            const float corr = __expf(Mx[rr] - Mn);
            Srun[rr] *= corr;
            #pragma unroll
            for (int nt = 0; nt < 4; nt++) {
                acco[nt][i0] *= corr;
                acco[nt][i1] *= corr;
            }
            Mx[rr] = Mn;
            float lsum = 0.0f;
            #pragma unroll
            for (int nt = 0; nt < 8; nt++) {
                const float p0 = __expf(accs[nt][i0] - Mn);
                const float p1 = __expf(accs[nt][i1] - Mn);
                lsum += p0 + p1;
                accs[nt][i0] = p0;
                accs[nt][i1] = p1;
            }
            lsum += __shfl_xor_sync(full, lsum, 1);
            lsum += __shfl_xor_sync(full, lsum, 2);
            Srun[rr] += lsum;
        }

        // ---- pack P to fp16 A-fragments (identity layout) ----
        unsigned ph[8][2];
        #pragma unroll
        for (int nt = 0; nt < 8; nt++) {
            ph[nt][0] = pack_h2(accs[nt][0], accs[nt][1]);
            ph[nt][1] = pack_h2(accs[nt][2], accs[nt][3]);
        }

        // ---- O += P V (single-term fp16 V) ----
        #pragma unroll
        for (int kcK = 0; kcK < 4; kcK++) {
            unsigned pa[4] = {ph[2 * kcK][0], ph[2 * kcK][1],
                              ph[2 * kcK + 1][0], ph[2 * kcK + 1][1]};
            #pragma unroll
            for (int vt = 0; vt < 4; vt++) {
                const int vb = (vt * 8 + g) * 72 + kcK * 16 + 2 * tg;
                unsigned bh[2];
                bh[0] = *(const unsigned*)&vsh[vb];
                bh[1] = *(const unsigned*)&vsh[vb + 8];
                mma_f16(acco[vt], pa, bh);
            }
        }
        __syncthreads();
    }

    // ---- epilogue: /S, +x, store ----
    const float inv0 = 1.0f / Srun[0];
    const float inv1 = 1.0f / Srun[1];
    #pragma unroll
    for (int nt = 0; nt < 4; nt++) {
        const int col = nt * 8 + 2 * tg;
        const long a0 = baseqk + (long)row0 * HD + col;
        const long a1 = baseqk + (long)(row0 + 8) * HD + col;
        float2 x0 = *(const float2*)(X + a0);
        float2 x1 = *(const float2*)(X + a1);
        float2 o0 = {acco[nt][0] * inv0 + x0.x, acco[nt][1] * inv0 + x0.y};
        float2 o1 = {acco[nt][2] * inv1 + x1.x, acco[nt][3] * inv1 + x1.y};
        *(float2*)(O + a0) = o0;
        *(float2*)(O + a1) = o1;
    }
}

// ---------------------------------------------------------------------------
// Launch
// ---------------------------------------------------------------------------
extern "C" void kernel_launch(void* const* d_in, const int* in_sizes, int n_in,
                              void* d_out, int out_size)
{
    const float* x     = (const float*)d_in[0];
    const float* scale = (const float*)d_in[1];
    const float* Wq    = (const float*)d_in[2];
    const float* WA    = (const float*)d_in[3];
    const float* W1    = (const float*)d_in[4];
    const float* W2    = (const float*)d_in[5];
    const float* g1    = (const float*)d_in[6];
    const float* g2    = (const float*)d_in[7];
    float* out = (float*)d_out;

    float *q, *vr, *res;
    __half *xhi, *xlo, *vpT, *vT, *hh, *h1;
    __half *waH, *wqhi, *wqlo, *w1H, *w2H;
    cudaGetSymbolAddress((void**)&q,    g_q);
    cudaGetSymbolAddress((void**)&vr,   g_vr);
    cudaGetSymbolAddress((void**)&res,  g_res);
    cudaGetSymbolAddress((void**)&xhi,  g_xhi);
    cudaGetSymbolAddress((void**)&xlo,  g_xlo);
    cudaGetSymbolAddress((void**)&vpT,  g_vpT);
    cudaGetSymbolAddress((void**)&vT,   g_vT);
    cudaGetSymbolAddress((void**)&hh,   g_hh);
    cudaGetSymbolAddress((void**)&h1,   g_h1);
    cudaGetSymbolAddress((void**)&waH,  g_waH);
    cudaGetSymbolAddress((void**)&wqhi, g_wqhi);
    cudaGetSymbolAddress((void**)&wqlo, g_wqlo);
    cudaGetSymbolAddress((void**)&w1H,  g_w1H);
    cudaGetSymbolAddress((void**)&w2H,  g_w2H);

    const int ROWS = BATCH * SEQ;  // 4096

    cudaFuncSetAttribute(gemm_wq, cudaFuncAttributeMaxDynamicSharedMemorySize,
                         WQ_SMEM_BYTES);
    cudaFuncSetAttribute(flash_h, cudaFuncAttributeMaxDynamicSharedMemorySize,
                         FLASH_SMEM_BYTES);
    cudaFuncSetAttribute(gemm_h<0>, cudaFuncAttributeMaxDynamicSharedMemorySize,
                         GH_SMEM_BYTES);
    cudaFuncSetAttribute(gemm_h<1>, cudaFuncAttributeMaxDynamicSharedMemorySize,
                         GH_SMEM_BYTES);
    cudaFuncSetAttribute(gemm_h<2>, cudaFuncAttributeMaxDynamicSharedMemorySize,
                         GH_SMEM_BYTES);

    // 0. fused weight prep (WA/W1/W2 convert, Wq split) — one launch
    weight_prep_kernel<<<(N_WA + 3 * N_W + 255) / 256, 256>>>(
        WA, W1, W2, Wq, waH, w1H, w2H, wqhi, wqlo);

    // 1. rmsnorm1 fused with hi/lo split (no fp32 xn buffer at all)
    rmsnorm_split_kernel<<<ROWS, 256>>>(x, g1, xhi, xlo);

    // 2. q = xn @ Wq^T  (compensated fp16, fp32-grade logits)
    gemm_wq<<<dim3(CH / 128, ROWS / 128, 1), 256, WQ_SMEM_BYTES>>>(
        xhi, xlo, wqhi, wqlo, q, ROWS, CH, CH);

    // 3. transpose-gather V' -> vpT[b][c][token] (from xhi)
    tr_gather_kernel<<<dim3(SEQ / 32, HEADS, BATCH), 256>>>(xhi, vpT);

    // 4. vr[b] = WA @ vp[b]  == NT(waH, vpT)
    gemm_h<0><<<dim3(CH / 128, SEQ / 128, BATCH), 256, GH_SMEM_BYTES>>>(
        waH, vpT, vr, nullptr, nullptr, SEQ, CH, SEQ,
        0, (long)CH * SEQ, (long)SEQ * CH);

    // 5. transpose vr -> vT[b][c][token] (half)
    tr_v_kernel<<<dim3(SEQ / 32, CH / 32, BATCH), 256>>>(vr, vT);

    // 6. attention (+x residual)
    flash_h<<<dim3(SEQ / 128, HEADS, BATCH), 256, FLASH_SMEM_BYTES>>>(
        q, xhi, xlo, vT, x, scale, res);

    // 7. hh = rmsnorm(res, g2) -> half
    rmsnorm_h_kernel<<<ROWS, 256>>>(res, g2, hh);

    // 8. h1 = gelu(hh @ W1^T) -> half
    gemm_h<1><<<dim3(CH / 128, ROWS / 128, 1), 256, GH_SMEM_BYTES>>>(
        hh, w1H, nullptr, h1, nullptr, ROWS, CH, CH, 0, 0, 0);

    // 9. out = h1 @ W2^T + res
    gemm_h<2><<<dim3(CH / 128, ROWS / 128, 1), 256, GH_SMEM_BYTES>>>(
        h1, w2H, out, nullptr, res, ROWS, CH, CH, 0, 0, 0);
}